// round 4
// baseline (speedup 1.0000x reference)
#include <cuda_runtime.h>

typedef unsigned long long ull;

// ---------------- problem constants ----------------
#define BATCH 2
#define CH    3
#define IMGH  384
#define IMGW  384
#define IMGPIX (IMGH*IMGW)
#define IMGSZ  (BATCH*CH*IMGPIX)
#define NB1   576   // blocks per batch in the p=1 stage (24*24)

// ---------------- scratch (device globals; no allocations allowed) ----------
__device__ float g_x3[IMGSZ];
__device__ float g_x6[IMGSZ];
__device__ float g_x9[IMGSZ];
__device__ float g_bmax[BATCH*NB1];

__device__ __forceinline__ float neg_inf() { return __int_as_float(0xff800000); }

// ---------------- packed f32x2 helpers --------------------------------------
__device__ __forceinline__ ull pk2(float lo, float hi) {
    ull r; asm("mov.b64 %0, {%1, %2};" : "=l"(r) : "f"(lo), "f"(hi)); return r;
}
__device__ __forceinline__ float2 up2(ull v) {
    float2 r; asm("mov.b64 {%0, %1}, %2;" : "=f"(r.x), "=f"(r.y) : "l"(v)); return r;
}
__device__ __forceinline__ void fma2(ull& d, ull a, ull b) {
    asm("fma.rn.f32x2 %0, %1, %2, %0;" : "+l"(d) : "l"(a), "l"(b));
}

// ---------------- swizzled shared-tile addressing ---------------------------
template<int P,int TILEH>
__device__ __forceinline__ int sm_idx(int c,int r,int col){
    int sw;
    if (P==1)      sw = col ^ ((r & 1) << 4);
    else if (P==3) sw = col ^ ((r & 3) << 3);
    else {
        int wc = col >> 1;
        int wcs = (wc + (((r >> 1) & 3) << 2)) & 15;
        sw = wcs * 2 + (col & 1);
    }
    return (c * TILEH + r) * 32 + sw;
}
template<int TILEH>
__device__ __forceinline__ int sm_idx2(int c,int r,int wc){ // P==2 float2-word index
    int wcs = (wc + (((r >> 1) & 3) << 2)) & 15;
    return (c * TILEH + r) * 16 + wcs;
}

// ============================================================================
// p=1 stage: one thread per window, all 6 heads fused (D=3, tiny registers).
// Also computes per-block image max for xg.
// ============================================================================
template<int TW,int TH>
__global__ void __launch_bounds__(TW*TH)
attn1_kernel(const float* __restrict__ in, float* __restrict__ out,
             const float* __restrict__ Wq, const float* __restrict__ bq,
             const float* __restrict__ Wk,
             const float* __restrict__ Wv, const float* __restrict__ bv,
             const float* __restrict__ hw)
{
    constexpr int P = 1, D = 3, HEADS = 6, DP = 4;
    constexpr int NTHR  = TW * TH;
    constexpr int TILEH = TH + 2;
    constexpr int TILEW = TW + 2;

    __shared__ __align__(16) float s_tile[CH * TILEH * 32];
    __shared__ __align__(16) float s_Gt [HEADS * D * DP];
    __shared__ __align__(16) float s_Wvt[HEADS * D * DP];
    __shared__ __align__(16) float s_gbp[HEADS * DP];
    __shared__ __align__(16) float s_bvp[HEADS * DP];
    __shared__ float s_red[NTHR / 32];

    const int tid = threadIdx.x;
    const int b   = blockIdx.z;
    const int wi0 = blockIdx.y * TH;
    const int wj0 = blockIdx.x * TW;
    const float scale = rsqrtf((float)D);

    for (int i = tid; i < HEADS * D * DP; i += NTHR) {
        int h = i / (D * DP); int r = i % (D * DP); int m = r / DP; int n = r % DP;
        float g = 0.f, wvv = 0.f;
        if (n < D) {
            const float* wk = Wk + h * D * D;
            const float* wq = Wq + h * D * D;
            float s = 0.f;
            #pragma unroll
            for (int e = 0; e < D; e++) s += wk[e * D + n] * wq[e * D + m];
            g   = s * scale;
            wvv = hw[h] * Wv[h * D * D + n * D + m];
        }
        s_Gt[i] = g; s_Wvt[i] = wvv;
    }
    for (int i = tid; i < HEADS * DP; i += NTHR) {
        int h = i / DP, n = i % DP;
        float gb = 0.f, bvv = 0.f;
        if (n < D) {
            const float* wk = Wk + h * D * D;
            float s = 0.f;
            #pragma unroll
            for (int e = 0; e < D; e++) s += bq[h * D + e] * wk[e * D + n];
            gb  = s * scale;
            bvv = hw[h] * bv[h * D + n];
        }
        s_gbp[i] = gb; s_bvp[i] = bvv;
    }

    const float* inb = in + (size_t)b * CH * IMGPIX;
    float lmax = neg_inf();
    for (int i = tid; i < CH * TILEH * TILEW; i += NTHR) {
        int c   = i / (TILEH * TILEW);
        int rem = i % (TILEH * TILEW);
        int tr  = rem / TILEW;
        int tc  = rem % TILEW;
        int rr = wi0 - 1 + tr; if (rr < 0) rr = -rr; else if (rr >= IMGH) rr = 2 * IMGH - 2 - rr;
        int cc = wj0 - 1 + tc; if (cc < 0) cc = -cc; else if (cc >= IMGW) cc = 2 * IMGW - 2 - cc;
        float v = inb[c * IMGPIX + rr * IMGW + cc];
        s_tile[sm_idx<P, TILEH>(c, tr, tc)] = v;
        lmax = fmaxf(lmax, v);
    }
    #pragma unroll
    for (int o = 16; o; o >>= 1) lmax = fmaxf(lmax, __shfl_xor_sync(0xffffffffu, lmax, o));
    if ((tid & 31) == 0) s_red[tid >> 5] = lmax;
    __syncthreads();
    if (tid == 0) {
        float m = s_red[0];
        #pragma unroll
        for (int w = 1; w < NTHR / 32; w++) m = fmaxf(m, s_red[w]);
        g_bmax[b * NB1 + blockIdx.y * gridDim.x + blockIdx.x] = m;
    }

    const int lwj = tid % TW;
    const int lwi = tid / TW;

    float tok4[D];
    #pragma unroll
    for (int c = 0; c < CH; c++)
        tok4[c] = s_tile[sm_idx<P, TILEH>(c, lwi + 1, lwj + 1)];

    float u[HEADS][DP];
    #pragma unroll
    for (int h = 0; h < HEADS; h++) {
        float4 v = *(const float4*)&s_gbp[h * DP];
        u[h][0] = v.x; u[h][1] = v.y; u[h][2] = v.z; u[h][3] = v.w;
    }
    #pragma unroll
    for (int h = 0; h < HEADS; h++)
        #pragma unroll
        for (int m = 0; m < D; m++) {
            float4 g = *(const float4*)&s_Gt[(h * D + m) * DP];
            float t = tok4[m];
            u[h][0] += g.x * t; u[h][1] += g.y * t; u[h][2] += g.z * t; u[h][3] += g.w * t;
        }

    float sc[HEADS][9], smax[HEADS];
    #pragma unroll
    for (int h = 0; h < HEADS; h++) smax[h] = neg_inf();

    #pragma unroll
    for (int di = 0; di < 3; di++)
    #pragma unroll
    for (int dj = 0; dj < 3; dj++) {
        float s[HEADS];
        #pragma unroll
        for (int h = 0; h < HEADS; h++) s[h] = 0.f;
        #pragma unroll
        for (int c = 0; c < CH; c++) {
            float v = s_tile[sm_idx<P, TILEH>(c, lwi + di, lwj + dj)];
            #pragma unroll
            for (int h = 0; h < HEADS; h++) s[h] += u[h][c] * v;
        }
        const int t = di * 3 + dj;
        #pragma unroll
        for (int h = 0; h < HEADS; h++) { sc[h][t] = s[h]; smax[h] = fmaxf(smax[h], s[h]); }
    }

    #pragma unroll
    for (int h = 0; h < HEADS; h++) {
        float den = 0.f;
        #pragma unroll
        for (int t = 0; t < 9; t++) { float e = __expf(sc[h][t] - smax[h]); sc[h][t] = e; den += e; }
        float inv = 1.f / den;
        #pragma unroll
        for (int t = 0; t < 9; t++) sc[h][t] *= inv;
    }

    float acc[HEADS][D];
    #pragma unroll
    for (int h = 0; h < HEADS; h++)
        #pragma unroll
        for (int d = 0; d < D; d++) acc[h][d] = 0.f;

    #pragma unroll
    for (int di = 0; di < 3; di++)
    #pragma unroll
    for (int dj = 0; dj < 3; dj++) {
        const int t = di * 3 + dj;
        #pragma unroll
        for (int c = 0; c < CH; c++) {
            float v = s_tile[sm_idx<P, TILEH>(c, lwi + di, lwj + dj)];
            #pragma unroll
            for (int h = 0; h < HEADS; h++) acc[h][c] += sc[h][t] * v;
        }
    }

    float part[DP];
    #pragma unroll
    for (int e = 0; e < DP; e++) part[e] = 0.f;
    #pragma unroll
    for (int h = 0; h < HEADS; h++) {
        float4 bvv = *(const float4*)&s_bvp[h * DP];
        part[0] += bvv.x; part[1] += bvv.y; part[2] += bvv.z; part[3] += bvv.w;
        #pragma unroll
        for (int m = 0; m < D; m++) {
            float4 w = *(const float4*)&s_Wvt[(h * D + m) * DP];
            float a = acc[h][m];
            part[0] += w.x * a; part[1] += w.y * a; part[2] += w.z * a; part[3] += w.w * a;
        }
    }

    float* outb = out + (size_t)b * CH * IMGPIX;
    const int wi = wi0 + lwi, wj = wj0 + lwj;
    #pragma unroll
    for (int c = 0; c < CH; c++)
        outb[c * IMGPIX + wi * IMGW + wj] = part[c];
}

// ============================================================================
// p=2 / p=3 stages: one warp-group per head (h = tid / NW). f32x2-packed
// projection matvecs; head partials combined via odd-stride shared scratch.
// ============================================================================
template<int P,int D,int HEADS,int TW,int TH>
__global__ void __launch_bounds__(TW*TH*HEADS)
attn_split(const float* __restrict__ in, float* __restrict__ out,
           const float* __restrict__ Wq, const float* __restrict__ bq,
           const float* __restrict__ Wk,
           const float* __restrict__ Wv, const float* __restrict__ bv,
           const float* __restrict__ hw)
{
    constexpr int PP    = P * P;
    constexpr int DP    = (D + 3) & ~3;
    constexpr int DH    = DP / 2;            // packed f32x2 count
    constexpr int DR    = D | 1;             // odd stride for conflict-free scratch
    constexpr int NW    = TW * TH;
    constexpr int NTHR  = NW * HEADS;
    constexpr int TILEH = (TH + 2) * P;
    constexpr int TILEW = (TW + 2) * P;
    static_assert(TILEW <= 32, "tile row must fit padded 32-float row");

    __shared__ __align__(16) float s_tile[CH * TILEH * 32];
    __shared__ __align__(16) float s_Gt [HEADS * D * DP];
    __shared__ __align__(16) float s_Wvt[HEADS * D * DP];
    __shared__ __align__(16) float s_gbp[HEADS * DP];
    __shared__ __align__(16) float s_bvp[HEADS * DP];
    __shared__ float s_part[(HEADS - 1) * NW * DR];

    const int tid = threadIdx.x;
    const int b   = blockIdx.z;
    const int wi0 = blockIdx.y * TH;
    const int wj0 = blockIdx.x * TW;
    const float scale = rsqrtf((float)D);

    for (int i = tid; i < HEADS * D * DP; i += NTHR) {
        int h = i / (D * DP); int r = i % (D * DP); int m = r / DP; int n = r % DP;
        float g = 0.f, wvv = 0.f;
        if (n < D) {
            const float* wk = Wk + h * D * D;
            const float* wq = Wq + h * D * D;
            float s = 0.f;
            #pragma unroll
            for (int e = 0; e < D; e++) s += wk[e * D + n] * wq[e * D + m];
            g   = s * scale;
            wvv = hw[h] * Wv[h * D * D + n * D + m];
        }
        s_Gt[i] = g; s_Wvt[i] = wvv;
    }
    for (int i = tid; i < HEADS * DP; i += NTHR) {
        int h = i / DP, n = i % DP;
        float gb = 0.f, bvv = 0.f;
        if (n < D) {
            const float* wk = Wk + h * D * D;
            float s = 0.f;
            #pragma unroll
            for (int e = 0; e < D; e++) s += bq[h * D + e] * wk[e * D + n];
            gb  = s * scale;
            bvv = hw[h] * bv[h * D + n];
        }
        s_gbp[i] = gb; s_bvp[i] = bvv;
    }

    const float* inb = in + (size_t)b * CH * IMGPIX;
    for (int i = tid; i < CH * TILEH * TILEW; i += NTHR) {
        int c   = i / (TILEH * TILEW);
        int rem = i % (TILEH * TILEW);
        int tr  = rem / TILEW;
        int tc  = rem % TILEW;
        int rr = (wi0 - 1) * P + tr; if (rr < 0) rr = -rr; else if (rr >= IMGH) rr = 2 * IMGH - 2 - rr;
        int cc = (wj0 - 1) * P + tc; if (cc < 0) cc = -cc; else if (cc >= IMGW) cc = 2 * IMGW - 2 - cc;
        s_tile[sm_idx<P, TILEH>(c, tr, tc)] = inb[c * IMGPIX + rr * IMGW + cc];
    }
    __syncthreads();

    const int w   = tid % NW;
    const int h   = tid / NW;
    const int lwj = w % TW;
    const int lwi = w / TW;

    // ---- center token ----
    float tok4[D];
    if constexpr (P == 2) {
        #pragma unroll
        for (int c = 0; c < CH; c++)
            #pragma unroll
            for (int pi = 0; pi < 2; pi++) {
                float2 v = ((const float2*)s_tile)[sm_idx2<TILEH>(c, (lwi + 1) * 2 + pi, lwj + 1)];
                tok4[c * 4 + pi * 2] = v.x; tok4[c * 4 + pi * 2 + 1] = v.y;
            }
    } else {
        #pragma unroll
        for (int c = 0; c < CH; c++)
            #pragma unroll
            for (int pi = 0; pi < P; pi++)
                #pragma unroll
                for (int pj = 0; pj < P; pj++)
                    tok4[c * PP + pi * P + pj] =
                        s_tile[sm_idx<P, TILEH>(c, (lwi + 1) * P + pi, (lwj + 1) * P + pj)];
    }

    // ---- u = G_h^T tok4 + gb_h  (f32x2 packed) ----
    ull u2[DH];
    #pragma unroll
    for (int e2 = 0; e2 < DH; e2 += 2) {
        ulonglong2 v = *(const ulonglong2*)&s_gbp[h * DP + e2 * 2];
        u2[e2] = v.x; u2[e2 + 1] = v.y;
    }
    #pragma unroll
    for (int m = 0; m < D; m++) {
        ull tp = pk2(tok4[m], tok4[m]);
        #pragma unroll
        for (int e2 = 0; e2 < DH; e2 += 2) {
            ulonglong2 g = *(const ulonglong2*)&s_Gt[(h * D + m) * DP + e2 * 2];
            fma2(u2[e2], g.x, tp);
            fma2(u2[e2 + 1], g.y, tp);
        }
    }
    float u[DP];
    #pragma unroll
    for (int e2 = 0; e2 < DH; e2++) {
        float2 v = up2(u2[e2]);
        u[e2 * 2] = v.x; u[e2 * 2 + 1] = v.y;
    }

    // ---- scores ----
    float sc[9];
    float smax = neg_inf();
    #pragma unroll
    for (int di = 0; di < 3; di++)
    #pragma unroll
    for (int dj = 0; dj < 3; dj++) {
        float s = 0.f;
        if constexpr (P == 2) {
            #pragma unroll
            for (int c = 0; c < CH; c++)
                #pragma unroll
                for (int pi = 0; pi < 2; pi++) {
                    float2 v = ((const float2*)s_tile)[sm_idx2<TILEH>(c, (lwi + di) * 2 + pi, lwj + dj)];
                    int e = c * 4 + pi * 2;
                    s += u[e] * v.x + u[e+1] * v.y;
                }
        } else {
            #pragma unroll
            for (int c = 0; c < CH; c++)
                #pragma unroll
                for (int pi = 0; pi < P; pi++)
                    #pragma unroll
                    for (int pj = 0; pj < P; pj++)
                        s += u[c * PP + pi * P + pj] *
                             s_tile[sm_idx<P, TILEH>(c, (lwi + di) * P + pi, (lwj + dj) * P + pj)];
        }
        sc[di * 3 + dj] = s;
        smax = fmaxf(smax, s);
    }

    float den = 0.f;
    #pragma unroll
    for (int t = 0; t < 9; t++) { float e = __expf(sc[t] - smax); sc[t] = e; den += e; }
    float inv = 1.f / den;
    #pragma unroll
    for (int t = 0; t < 9; t++) sc[t] *= inv;

    // ---- weighted token sum ----
    float acc[D];
    #pragma unroll
    for (int d = 0; d < D; d++) acc[d] = 0.f;
    #pragma unroll
    for (int di = 0; di < 3; di++)
    #pragma unroll
    for (int dj = 0; dj < 3; dj++) {
        const float a = sc[di * 3 + dj];
        if constexpr (P == 2) {
            #pragma unroll
            for (int c = 0; c < CH; c++)
                #pragma unroll
                for (int pi = 0; pi < 2; pi++) {
                    float2 v = ((const float2*)s_tile)[sm_idx2<TILEH>(c, (lwi + di) * 2 + pi, lwj + dj)];
                    int e = c * 4 + pi * 2;
                    acc[e] += a * v.x; acc[e+1] += a * v.y;
                }
        } else {
            #pragma unroll
            for (int c = 0; c < CH; c++)
                #pragma unroll
                for (int pi = 0; pi < P; pi++)
                    #pragma unroll
                    for (int pj = 0; pj < P; pj++)
                        acc[c * PP + pi * P + pj] +=
                            a * s_tile[sm_idx<P, TILEH>(c, (lwi + di) * P + pi, (lwj + dj) * P + pj)];
        }
    }

    // ---- projection (hw folded, f32x2 packed) ----
    ull p2a[DH];
    #pragma unroll
    for (int e2 = 0; e2 < DH; e2 += 2) {
        ulonglong2 v = *(const ulonglong2*)&s_bvp[h * DP + e2 * 2];
        p2a[e2] = v.x; p2a[e2 + 1] = v.y;
    }
    #pragma unroll
    for (int m = 0; m < D; m++) {
        ull ap = pk2(acc[m], acc[m]);
        #pragma unroll
        for (int e2 = 0; e2 < DH; e2 += 2) {
            ulonglong2 wv = *(const ulonglong2*)&s_Wvt[(h * D + m) * DP + e2 * 2];
            fma2(p2a[e2], wv.x, ap);
            fma2(p2a[e2 + 1], wv.y, ap);
        }
    }
    float part[DP];
    #pragma unroll
    for (int e2 = 0; e2 < DH; e2++) {
        float2 v = up2(p2a[e2]);
        part[e2 * 2] = v.x; part[e2 * 2 + 1] = v.y;
    }

    // ---- combine heads ----
    if (h > 0) {
        #pragma unroll
        for (int e = 0; e < D; e++)
            s_part[(h - 1) * NW * DR + w * DR + e] = part[e];
    }
    __syncthreads();
    if (h == 0) {
        #pragma unroll
        for (int s = 0; s < HEADS - 1; s++)
            #pragma unroll
            for (int e = 0; e < D; e++)
                part[e] += s_part[s * NW * DR + w * DR + e];

        float* outb = out + (size_t)b * CH * IMGPIX;
        const int wi = wi0 + lwi, wj = wj0 + lwj;
        if constexpr (P == 2) {
            #pragma unroll
            for (int c = 0; c < CH; c++)
                #pragma unroll
                for (int pi = 0; pi < 2; pi++)
                    *(float2*)&outb[c * IMGPIX + (wi * 2 + pi) * IMGW + wj * 2] =
                        make_float2(part[c * 4 + pi * 2], part[c * 4 + pi * 2 + 1]);
        } else {
            #pragma unroll
            for (int c = 0; c < CH; c++)
                #pragma unroll
                for (int pi = 0; pi < P; pi++)
                    #pragma unroll
                    for (int pj = 0; pj < P; pj++)
                        outb[c * IMGPIX + (wi * P + pi) * IMGW + (wj * P + pj)] =
                            part[c * PP + pi * P + pj];
        }
    }
}

// ============================================================================
// fused conv0 (5x5, zero pad 2, cat[x9,x6,x3]) + dehaze epilogue.
// 4 px/thread as 2x f32x2 pairs; duplicated-pair weights in smem.
// ============================================================================
#define FB_X 8    // threads in x (each does 4 px)
#define FB_Y 8
#define FOUT_X 32
#define FOUT_Y 8

__global__ void __launch_bounds__(FB_X*FB_Y)
final_kernel(const float* __restrict__ x,
             const float* __restrict__ conv_w, const float* __restrict__ conv_b,
             float* __restrict__ out)
{
    constexpr int TEH = FOUT_Y + 4, TEW = FOUT_X + 4;   // 12 x 36
    constexpr int NTHR = FB_X * FB_Y;                   // 64
    __shared__ __align__(16) float s_t[9][TEH][TEW];
    __shared__ __align__(16) ull s_wd[3][9][5][6];      // {w,w} pairs, kw padded to 6
    __shared__ float s_b[3];
    __shared__ float s_red[NTHR / 32];

    const int tid = threadIdx.y * FB_X + threadIdx.x;
    for (int i = tid; i < 675; i += NTHR) {
        int co = i / 225; int r = i % 225; int ci = r / 25; int kk = r % 25;
        float wv = conv_w[i];
        s_wd[co][ci][kk / 5][kk % 5] = pk2(wv, wv);
    }
    if (tid < 3) s_b[tid] = conv_b[tid];

    const int b  = blockIdx.z;
    const int y0 = blockIdx.y * FOUT_Y;
    const int x0 = blockIdx.x * FOUT_X;

    // xg = image max (reduced from p=1 per-block maxes)
    float m = neg_inf();
    for (int i = tid; i < NB1; i += NTHR) m = fmaxf(m, g_bmax[b * NB1 + i]);
    #pragma unroll
    for (int o = 16; o; o >>= 1) m = fmaxf(m, __shfl_xor_sync(0xffffffffu, m, o));
    if ((tid & 31) == 0) s_red[tid >> 5] = m;

    for (int i = tid; i < 9 * TEH * TEW; i += NTHR) {
        int ci  = i / (TEH * TEW);
        int rem = i % (TEH * TEW);
        int ty  = rem / TEW;
        int tx  = rem % TEW;
        int gy = y0 + ty - 2, gx = x0 + tx - 2;
        float v = 0.f;
        if (gy >= 0 && gy < IMGH && gx >= 0 && gx < IMGW) {
            const float* src = (ci < 3) ? g_x9 : (ci < 6) ? g_x6 : g_x3;
            v = src[(((size_t)b * CH + (ci % 3)) * IMGH + gy) * IMGW + gx];
        }
        s_t[ci][ty][tx] = v;
    }
    __syncthreads();

    float xg = s_red[0];
    #pragma unroll
    for (int w = 1; w < NTHR / 32; w++) xg = fmaxf(xg, s_red[w]);

    const int ty  = threadIdx.y;
    const int tx4 = threadIdx.x * 4;

    ull acc2[3][2];
    #pragma unroll
    for (int co = 0; co < 3; co++) {
        ull bz = pk2(s_b[co], s_b[co]);
        acc2[co][0] = bz; acc2[co][1] = bz;
    }

    #pragma unroll
    for (int ci = 0; ci < 9; ci++)
        #pragma unroll
        for (int kh = 0; kh < 5; kh++) {
            const float* rowp = &s_t[ci][ty + kh][tx4];
            float4 a = *(const float4*)(rowp);
            float4 c = *(const float4*)(rowp + 4);
            float f0=a.x, f1=a.y, f2=a.z, f3=a.w, f4=c.x, f5=c.y, f6=c.z, f7=c.w;
            // sliding pairs P[k] = {f[k], f[k+1]}, k = 0..6
            ull pr[7];
            pr[0]=pk2(f0,f1); pr[1]=pk2(f1,f2); pr[2]=pk2(f2,f3); pr[3]=pk2(f3,f4);
            pr[4]=pk2(f4,f5); pr[5]=pk2(f5,f6); pr[6]=pk2(f6,f7);
            #pragma unroll
            for (int co = 0; co < 3; co++) {
                ull wv[5];
                ulonglong2 w01 = *(const ulonglong2*)&s_wd[co][ci][kh][0];
                ulonglong2 w23 = *(const ulonglong2*)&s_wd[co][ci][kh][2];
                wv[0]=w01.x; wv[1]=w01.y; wv[2]=w23.x; wv[3]=w23.y;
                wv[4]=s_wd[co][ci][kh][4];
                #pragma unroll
                for (int kw = 0; kw < 5; kw++) {
                    fma2(acc2[co][0], wv[kw], pr[kw]);
                    fma2(acc2[co][1], wv[kw], pr[kw + 2]);
                }
            }
        }

    const int gy = y0 + ty, gx = x0 + tx4;
    #pragma unroll
    for (int co = 0; co < 3; co++) {
        size_t idx = (((size_t)b * CH + co) * IMGH + gy) * IMGW + gx;
        float4 xv = *(const float4*)&x[idx];
        float2 lo = up2(acc2[co][0]);
        float2 hi = up2(acc2[co][1]);
        float4 r;
        float x0v;
        x0v = fmaxf(lo.x, 0.f); r.x = fmaxf(xv.x * x0v + (xg - x0v), 0.f);
        x0v = fmaxf(lo.y, 0.f); r.y = fmaxf(xv.y * x0v + (xg - x0v), 0.f);
        x0v = fmaxf(hi.x, 0.f); r.z = fmaxf(xv.z * x0v + (xg - x0v), 0.f);
        x0v = fmaxf(hi.y, 0.f); r.w = fmaxf(xv.w * x0v + (xg - x0v), 0.f);
        *(float4*)&out[idx] = r;
    }
}

// ---------------- launch ----------------------------------------------------
extern "C" void kernel_launch(void* const* d_in, const int* in_sizes, int n_in,
                              void* d_out, int out_size)
{
    (void)in_sizes; (void)n_in; (void)out_size;

    const float* x    = (const float*)d_in[0];
    const float* w3q  = (const float*)d_in[1];
    const float* b3q  = (const float*)d_in[2];
    const float* w3k  = (const float*)d_in[3];
    const float* w3v  = (const float*)d_in[5];
    const float* b3v  = (const float*)d_in[6];
    const float* hw3  = (const float*)d_in[7];
    const float* w6q  = (const float*)d_in[8];
    const float* b6q  = (const float*)d_in[9];
    const float* w6k  = (const float*)d_in[10];
    const float* w6v  = (const float*)d_in[12];
    const float* b6v  = (const float*)d_in[13];
    const float* hw6  = (const float*)d_in[14];
    const float* w9q  = (const float*)d_in[15];
    const float* b9q  = (const float*)d_in[16];
    const float* w9k  = (const float*)d_in[17];
    const float* w9v  = (const float*)d_in[19];
    const float* b9v  = (const float*)d_in[20];
    const float* hw9  = (const float*)d_in[21];
    const float* cw   = (const float*)d_in[22];
    const float* cb   = (const float*)d_in[23];

    float *x3, *x6, *x9;
    cudaGetSymbolAddress((void**)&x3, g_x3);
    cudaGetSymbolAddress((void**)&x6, g_x6);
    cudaGetSymbolAddress((void**)&x9, g_x9);

    // stage p=1: 384x384 windows, 16x16 windows/block, 6 heads fused (+ image max)
    attn1_kernel<16, 16><<<dim3(24, 24, BATCH), 256>>>(x,  x3, w3q, b3q, w3k, w3v, b3v, hw3);
    // stage p=2: 192x192 windows, 8x8 windows/block x 4 head-groups = 256 thr
    attn_split<2, 12, 4, 8, 8><<<dim3(24, 24, BATCH), 256>>>(x3, x6, w6q, b6q, w6k, w6v, b6v, hw6);
    // stage p=3: 128x128 windows, 8x8 windows/block x 2 head-groups = 128 thr
    attn_split<3, 27, 2, 8, 8><<<dim3(16, 16, BATCH), 128>>>(x6, x9, w9q, b9q, w9k, w9v, b9v, hw9);

    final_kernel<<<dim3(IMGW / FOUT_X, IMGH / FOUT_Y, BATCH), dim3(FB_X, FB_Y)>>>(x, cw, cb, (float*)d_out);
}

// round 5
// speedup vs baseline: 1.7100x; 1.7100x over previous
#include <cuda_runtime.h>

// ---------------- problem constants ----------------
#define BATCH 2
#define CH    3
#define IMGH  384
#define IMGW  384
#define IMGPIX (IMGH*IMGW)
#define IMGSZ  (BATCH*CH*IMGPIX)
#define NB1   576   // blocks per batch in the p=1 stage (24*24)

// ---------------- scratch (device globals; no allocations allowed) ----------
__device__ float g_x3[IMGSZ];
__device__ float g_x6[IMGSZ];
__device__ float g_x9[IMGSZ];
__device__ float g_bmax[BATCH*NB1];

__device__ __forceinline__ float neg_inf() { return __int_as_float(0xff800000); }

// ---------------- swizzled shared-tile addressing ---------------------------
template<int P,int TILEH>
__device__ __forceinline__ int sm_idx(int c,int r,int col){
    int sw;
    if (P==1)      sw = col ^ ((r & 1) << 4);
    else if (P==3) sw = col ^ ((r & 3) << 3);
    else {
        int wc = col >> 1;
        int wcs = (wc + (((r >> 1) & 3) << 2)) & 15;
        sw = wcs * 2 + (col & 1);
    }
    return (c * TILEH + r) * 32 + sw;
}
template<int TILEH>
__device__ __forceinline__ int sm_idx2(int c,int r,int wc){ // P==2 float2-word index
    int wcs = (wc + (((r >> 1) & 3) << 2)) & 15;
    return (c * TILEH + r) * 16 + wcs;
}

// ============================================================================
// p=1 stage: one thread per window, all 6 heads fused (D=3, tiny registers).
// Also computes per-block image max for xg.
// ============================================================================
template<int TW,int TH>
__global__ void __launch_bounds__(TW*TH)
attn1_kernel(const float* __restrict__ in, float* __restrict__ out,
             const float* __restrict__ Wq, const float* __restrict__ bq,
             const float* __restrict__ Wk,
             const float* __restrict__ Wv, const float* __restrict__ bv,
             const float* __restrict__ hw)
{
    constexpr int P = 1, D = 3, HEADS = 6, DP = 4;
    constexpr int NTHR  = TW * TH;
    constexpr int TILEH = TH + 2;
    constexpr int TILEW = TW + 2;

    __shared__ __align__(16) float s_tile[CH * TILEH * 32];
    __shared__ __align__(16) float s_Gt [HEADS * D * DP];
    __shared__ __align__(16) float s_Wvt[HEADS * D * DP];
    __shared__ __align__(16) float s_gbp[HEADS * DP];
    __shared__ __align__(16) float s_bvp[HEADS * DP];
    __shared__ float s_red[NTHR / 32];

    const int tid = threadIdx.x;
    const int b   = blockIdx.z;
    const int wi0 = blockIdx.y * TH;
    const int wj0 = blockIdx.x * TW;
    const float scale = rsqrtf((float)D);

    for (int i = tid; i < HEADS * D * DP; i += NTHR) {
        int h = i / (D * DP); int r = i % (D * DP); int m = r / DP; int n = r % DP;
        float g = 0.f, wvv = 0.f;
        if (n < D) {
            const float* wk = Wk + h * D * D;
            const float* wq = Wq + h * D * D;
            float s = 0.f;
            #pragma unroll
            for (int e = 0; e < D; e++) s += wk[e * D + n] * wq[e * D + m];
            g   = s * scale;
            wvv = hw[h] * Wv[h * D * D + n * D + m];
        }
        s_Gt[i] = g; s_Wvt[i] = wvv;
    }
    for (int i = tid; i < HEADS * DP; i += NTHR) {
        int h = i / DP, n = i % DP;
        float gb = 0.f, bvv = 0.f;
        if (n < D) {
            const float* wk = Wk + h * D * D;
            float s = 0.f;
            #pragma unroll
            for (int e = 0; e < D; e++) s += bq[h * D + e] * wk[e * D + n];
            gb  = s * scale;
            bvv = hw[h] * bv[h * D + n];
        }
        s_gbp[i] = gb; s_bvp[i] = bvv;
    }

    const float* inb = in + (size_t)b * CH * IMGPIX;
    float lmax = neg_inf();
    for (int i = tid; i < CH * TILEH * TILEW; i += NTHR) {
        int c   = i / (TILEH * TILEW);
        int rem = i % (TILEH * TILEW);
        int tr  = rem / TILEW;
        int tc  = rem % TILEW;
        int rr = wi0 - 1 + tr; if (rr < 0) rr = -rr; else if (rr >= IMGH) rr = 2 * IMGH - 2 - rr;
        int cc = wj0 - 1 + tc; if (cc < 0) cc = -cc; else if (cc >= IMGW) cc = 2 * IMGW - 2 - cc;
        float v = inb[c * IMGPIX + rr * IMGW + cc];
        s_tile[sm_idx<P, TILEH>(c, tr, tc)] = v;
        lmax = fmaxf(lmax, v);
    }
    #pragma unroll
    for (int o = 16; o; o >>= 1) lmax = fmaxf(lmax, __shfl_xor_sync(0xffffffffu, lmax, o));
    if ((tid & 31) == 0) s_red[tid >> 5] = lmax;
    __syncthreads();
    if (tid == 0) {
        float m = s_red[0];
        #pragma unroll
        for (int w = 1; w < NTHR / 32; w++) m = fmaxf(m, s_red[w]);
        g_bmax[b * NB1 + blockIdx.y * gridDim.x + blockIdx.x] = m;
    }

    const int lwj = tid % TW;
    const int lwi = tid / TW;

    float tok4[D];
    #pragma unroll
    for (int c = 0; c < CH; c++)
        tok4[c] = s_tile[sm_idx<P, TILEH>(c, lwi + 1, lwj + 1)];

    float u[HEADS][DP];
    #pragma unroll
    for (int h = 0; h < HEADS; h++) {
        float4 v = *(const float4*)&s_gbp[h * DP];
        u[h][0] = v.x; u[h][1] = v.y; u[h][2] = v.z; u[h][3] = v.w;
    }
    #pragma unroll
    for (int h = 0; h < HEADS; h++)
        #pragma unroll
        for (int m = 0; m < D; m++) {
            float4 g = *(const float4*)&s_Gt[(h * D + m) * DP];
            float t = tok4[m];
            u[h][0] += g.x * t; u[h][1] += g.y * t; u[h][2] += g.z * t; u[h][3] += g.w * t;
        }

    float sc[HEADS][9], smax[HEADS];
    #pragma unroll
    for (int h = 0; h < HEADS; h++) smax[h] = neg_inf();

    #pragma unroll
    for (int di = 0; di < 3; di++)
    #pragma unroll
    for (int dj = 0; dj < 3; dj++) {
        float s[HEADS];
        #pragma unroll
        for (int h = 0; h < HEADS; h++) s[h] = 0.f;
        #pragma unroll
        for (int c = 0; c < CH; c++) {
            float v = s_tile[sm_idx<P, TILEH>(c, lwi + di, lwj + dj)];
            #pragma unroll
            for (int h = 0; h < HEADS; h++) s[h] += u[h][c] * v;
        }
        const int t = di * 3 + dj;
        #pragma unroll
        for (int h = 0; h < HEADS; h++) { sc[h][t] = s[h]; smax[h] = fmaxf(smax[h], s[h]); }
    }

    #pragma unroll
    for (int h = 0; h < HEADS; h++) {
        float den = 0.f;
        #pragma unroll
        for (int t = 0; t < 9; t++) { float e = __expf(sc[h][t] - smax[h]); sc[h][t] = e; den += e; }
        float inv = 1.f / den;
        #pragma unroll
        for (int t = 0; t < 9; t++) sc[h][t] *= inv;
    }

    float acc[HEADS][D];
    #pragma unroll
    for (int h = 0; h < HEADS; h++)
        #pragma unroll
        for (int d = 0; d < D; d++) acc[h][d] = 0.f;

    #pragma unroll
    for (int di = 0; di < 3; di++)
    #pragma unroll
    for (int dj = 0; dj < 3; dj++) {
        const int t = di * 3 + dj;
        #pragma unroll
        for (int c = 0; c < CH; c++) {
            float v = s_tile[sm_idx<P, TILEH>(c, lwi + di, lwj + dj)];
            #pragma unroll
            for (int h = 0; h < HEADS; h++) acc[h][c] += sc[h][t] * v;
        }
    }

    float part[DP];
    #pragma unroll
    for (int e = 0; e < DP; e++) part[e] = 0.f;
    #pragma unroll
    for (int h = 0; h < HEADS; h++) {
        float4 bvv = *(const float4*)&s_bvp[h * DP];
        part[0] += bvv.x; part[1] += bvv.y; part[2] += bvv.z; part[3] += bvv.w;
        #pragma unroll
        for (int m = 0; m < D; m++) {
            float4 w = *(const float4*)&s_Wvt[(h * D + m) * DP];
            float a = acc[h][m];
            part[0] += w.x * a; part[1] += w.y * a; part[2] += w.z * a; part[3] += w.w * a;
        }
    }

    float* outb = out + (size_t)b * CH * IMGPIX;
    const int wi = wi0 + lwi, wj = wj0 + lwj;
    #pragma unroll
    for (int c = 0; c < CH; c++)
        outb[c * IMGPIX + wi * IMGW + wj] = part[c];
}

// ============================================================================
// p=2 / p=3 stages: one warp-group per head (h = tid / NW). Token LDS keeps the
// conflict-free lane layout; weight reads are warp-uniform float4 broadcasts.
// Head partials combined via odd-stride shared scratch.  (round-3 version)
// ============================================================================
template<int P,int D,int HEADS,int TW,int TH>
__global__ void __launch_bounds__(TW*TH*HEADS)
attn_split(const float* __restrict__ in, float* __restrict__ out,
           const float* __restrict__ Wq, const float* __restrict__ bq,
           const float* __restrict__ Wk,
           const float* __restrict__ Wv, const float* __restrict__ bv,
           const float* __restrict__ hw)
{
    constexpr int PP    = P * P;
    constexpr int DP    = (D + 3) & ~3;
    constexpr int DR    = D | 1;            // odd stride for conflict-free scratch
    constexpr int NW    = TW * TH;
    constexpr int NTHR  = NW * HEADS;
    constexpr int TILEH = (TH + 2) * P;
    constexpr int TILEW = (TW + 2) * P;
    static_assert(TILEW <= 32, "tile row must fit padded 32-float row");

    __shared__ __align__(16) float s_tile[CH * TILEH * 32];
    __shared__ __align__(16) float s_Gt [HEADS * D * DP];
    __shared__ __align__(16) float s_Wvt[HEADS * D * DP];
    __shared__ __align__(16) float s_gbp[HEADS * DP];
    __shared__ __align__(16) float s_bvp[HEADS * DP];
    __shared__ float s_part[(HEADS - 1) * NW * DR];

    const int tid = threadIdx.x;
    const int b   = blockIdx.z;
    const int wi0 = blockIdx.y * TH;
    const int wj0 = blockIdx.x * TW;
    const float scale = rsqrtf((float)D);

    for (int i = tid; i < HEADS * D * DP; i += NTHR) {
        int h = i / (D * DP); int r = i % (D * DP); int m = r / DP; int n = r % DP;
        float g = 0.f, wvv = 0.f;
        if (n < D) {
            const float* wk = Wk + h * D * D;
            const float* wq = Wq + h * D * D;
            float s = 0.f;
            #pragma unroll
            for (int e = 0; e < D; e++) s += wk[e * D + n] * wq[e * D + m];
            g   = s * scale;
            wvv = hw[h] * Wv[h * D * D + n * D + m];
        }
        s_Gt[i] = g; s_Wvt[i] = wvv;
    }
    for (int i = tid; i < HEADS * DP; i += NTHR) {
        int h = i / DP, n = i % DP;
        float gb = 0.f, bvv = 0.f;
        if (n < D) {
            const float* wk = Wk + h * D * D;
            float s = 0.f;
            #pragma unroll
            for (int e = 0; e < D; e++) s += bq[h * D + e] * wk[e * D + n];
            gb  = s * scale;
            bvv = hw[h] * bv[h * D + n];
        }
        s_gbp[i] = gb; s_bvp[i] = bvv;
    }

    const float* inb = in + (size_t)b * CH * IMGPIX;
    for (int i = tid; i < CH * TILEH * TILEW; i += NTHR) {
        int c   = i / (TILEH * TILEW);
        int rem = i % (TILEH * TILEW);
        int tr  = rem / TILEW;
        int tc  = rem % TILEW;
        int rr = (wi0 - 1) * P + tr; if (rr < 0) rr = -rr; else if (rr >= IMGH) rr = 2 * IMGH - 2 - rr;
        int cc = (wj0 - 1) * P + tc; if (cc < 0) cc = -cc; else if (cc >= IMGW) cc = 2 * IMGW - 2 - cc;
        s_tile[sm_idx<P, TILEH>(c, tr, tc)] = inb[c * IMGPIX + rr * IMGW + cc];
    }
    __syncthreads();

    const int w   = tid % NW;
    const int h   = tid / NW;
    const int lwj = w % TW;
    const int lwi = w / TW;

    // ---- center token ----
    float tok4[D];
    if constexpr (P == 2) {
        #pragma unroll
        for (int c = 0; c < CH; c++)
            #pragma unroll
            for (int pi = 0; pi < 2; pi++) {
                float2 v = ((const float2*)s_tile)[sm_idx2<TILEH>(c, (lwi + 1) * 2 + pi, lwj + 1)];
                tok4[c * 4 + pi * 2] = v.x; tok4[c * 4 + pi * 2 + 1] = v.y;
            }
    } else {
        #pragma unroll
        for (int c = 0; c < CH; c++)
            #pragma unroll
            for (int pi = 0; pi < P; pi++)
                #pragma unroll
                for (int pj = 0; pj < P; pj++)
                    tok4[c * PP + pi * P + pj] =
                        s_tile[sm_idx<P, TILEH>(c, (lwi + 1) * P + pi, (lwj + 1) * P + pj)];
    }

    // ---- u = G_h^T tok4 + gb_h ----
    float u[DP];
    #pragma unroll
    for (int e4 = 0; e4 < DP; e4 += 4) {
        float4 v = *(const float4*)&s_gbp[h * DP + e4];
        u[e4] = v.x; u[e4+1] = v.y; u[e4+2] = v.z; u[e4+3] = v.w;
    }
    #pragma unroll
    for (int m = 0; m < D; m++) {
        float t = tok4[m];
        #pragma unroll
        for (int e4 = 0; e4 < DP; e4 += 4) {
            float4 g = *(const float4*)&s_Gt[(h * D + m) * DP + e4];
            u[e4]   += g.x * t; u[e4+1] += g.y * t;
            u[e4+2] += g.z * t; u[e4+3] += g.w * t;
        }
    }

    // ---- scores ----
    float sc[9];
    float smax = neg_inf();
    #pragma unroll
    for (int di = 0; di < 3; di++)
    #pragma unroll
    for (int dj = 0; dj < 3; dj++) {
        float s = 0.f;
        if constexpr (P == 2) {
            #pragma unroll
            for (int c = 0; c < CH; c++)
                #pragma unroll
                for (int pi = 0; pi < 2; pi++) {
                    float2 v = ((const float2*)s_tile)[sm_idx2<TILEH>(c, (lwi + di) * 2 + pi, lwj + dj)];
                    int e = c * 4 + pi * 2;
                    s += u[e] * v.x + u[e+1] * v.y;
                }
        } else {
            #pragma unroll
            for (int c = 0; c < CH; c++)
                #pragma unroll
                for (int pi = 0; pi < P; pi++)
                    #pragma unroll
                    for (int pj = 0; pj < P; pj++)
                        s += u[c * PP + pi * P + pj] *
                             s_tile[sm_idx<P, TILEH>(c, (lwi + di) * P + pi, (lwj + dj) * P + pj)];
        }
        sc[di * 3 + dj] = s;
        smax = fmaxf(smax, s);
    }

    float den = 0.f;
    #pragma unroll
    for (int t = 0; t < 9; t++) { float e = __expf(sc[t] - smax); sc[t] = e; den += e; }
    float inv = 1.f / den;
    #pragma unroll
    for (int t = 0; t < 9; t++) sc[t] *= inv;

    // ---- weighted token sum ----
    float acc[D];
    #pragma unroll
    for (int d = 0; d < D; d++) acc[d] = 0.f;
    #pragma unroll
    for (int di = 0; di < 3; di++)
    #pragma unroll
    for (int dj = 0; dj < 3; dj++) {
        const float a = sc[di * 3 + dj];
        if constexpr (P == 2) {
            #pragma unroll
            for (int c = 0; c < CH; c++)
                #pragma unroll
                for (int pi = 0; pi < 2; pi++) {
                    float2 v = ((const float2*)s_tile)[sm_idx2<TILEH>(c, (lwi + di) * 2 + pi, lwj + dj)];
                    int e = c * 4 + pi * 2;
                    acc[e] += a * v.x; acc[e+1] += a * v.y;
                }
        } else {
            #pragma unroll
            for (int c = 0; c < CH; c++)
                #pragma unroll
                for (int pi = 0; pi < P; pi++)
                    #pragma unroll
                    for (int pj = 0; pj < P; pj++)
                        acc[c * PP + pi * P + pj] +=
                            a * s_tile[sm_idx<P, TILEH>(c, (lwi + di) * P + pi, (lwj + dj) * P + pj)];
        }
    }

    // ---- projection (hw folded) ----
    float part[DP];
    #pragma unroll
    for (int e4 = 0; e4 < DP; e4 += 4) {
        float4 v = *(const float4*)&s_bvp[h * DP + e4];
        part[e4] = v.x; part[e4+1] = v.y; part[e4+2] = v.z; part[e4+3] = v.w;
    }
    #pragma unroll
    for (int m = 0; m < D; m++) {
        float a = acc[m];
        #pragma unroll
        for (int e4 = 0; e4 < DP; e4 += 4) {
            float4 wv = *(const float4*)&s_Wvt[(h * D + m) * DP + e4];
            part[e4]   += wv.x * a; part[e4+1] += wv.y * a;
            part[e4+2] += wv.z * a; part[e4+3] += wv.w * a;
        }
    }

    // ---- combine heads ----
    if (h > 0) {
        #pragma unroll
        for (int e = 0; e < D; e++)
            s_part[(h - 1) * NW * DR + w * DR + e] = part[e];
    }
    __syncthreads();
    if (h == 0) {
        #pragma unroll
        for (int s = 0; s < HEADS - 1; s++)
            #pragma unroll
            for (int e = 0; e < D; e++)
                part[e] += s_part[s * NW * DR + w * DR + e];

        float* outb = out + (size_t)b * CH * IMGPIX;
        const int wi = wi0 + lwi, wj = wj0 + lwj;
        if constexpr (P == 2) {
            #pragma unroll
            for (int c = 0; c < CH; c++)
                #pragma unroll
                for (int pi = 0; pi < 2; pi++)
                    *(float2*)&outb[c * IMGPIX + (wi * 2 + pi) * IMGW + wj * 2] =
                        make_float2(part[c * 4 + pi * 2], part[c * 4 + pi * 2 + 1]);
        } else {
            #pragma unroll
            for (int c = 0; c < CH; c++)
                #pragma unroll
                for (int pi = 0; pi < P; pi++)
                    #pragma unroll
                    for (int pj = 0; pj < P; pj++)
                        outb[c * IMGPIX + (wi * P + pi) * IMGW + (wj * P + pj)] =
                            part[c * PP + pi * P + pj];
        }
    }
}

// ============================================================================
// fused conv0 (5x5, zero pad 2, cat[x9,x6,x3]) + dehaze epilogue.
// Channel-split: thread (tx,ty,co) computes 4 px of output channel co.
// 3x the threads of round 3 -> ~47 warps/SM at the same grid.
// ============================================================================
#define FB_X 8    // threads in x (each does 4 px)
#define FB_Y 16
#define FOUT_X 32
#define FOUT_Y 16

__global__ void __launch_bounds__(FB_X*FB_Y*3)
final_kernel(const float* __restrict__ x,
             const float* __restrict__ conv_w, const float* __restrict__ conv_b,
             float* __restrict__ out)
{
    constexpr int TEH = FOUT_Y + 4, TEW = FOUT_X + 4;   // 20 x 36
    constexpr int NTHR = FB_X * FB_Y * 3;               // 384
    __shared__ __align__(16) float s_t[9][TEH][TEW];
    __shared__ __align__(16) float s_w4[3][9][5][8];    // weight rows padded to 8
    __shared__ float s_b[3];
    __shared__ float s_red[NTHR / 32];

    const int tid = (threadIdx.z * FB_Y + threadIdx.y) * FB_X + threadIdx.x;
    for (int i = tid; i < 675; i += NTHR) {
        int co = i / 225; int r = i % 225; int ci = r / 25; int kk = r % 25;
        s_w4[co][ci][kk / 5][kk % 5] = conv_w[i];
    }
    if (tid < 3) s_b[tid] = conv_b[tid];

    const int b  = blockIdx.z;
    const int y0 = blockIdx.y * FOUT_Y;
    const int x0 = blockIdx.x * FOUT_X;

    // xg = image max (reduced from p=1 per-block maxes)
    float m = neg_inf();
    for (int i = tid; i < NB1; i += NTHR) m = fmaxf(m, g_bmax[b * NB1 + i]);
    #pragma unroll
    for (int o = 16; o; o >>= 1) m = fmaxf(m, __shfl_xor_sync(0xffffffffu, m, o));
    if ((tid & 31) == 0) s_red[tid >> 5] = m;

    for (int i = tid; i < 9 * TEH * TEW; i += NTHR) {
        int ci  = i / (TEH * TEW);
        int rem = i % (TEH * TEW);
        int ty  = rem / TEW;
        int tx  = rem % TEW;
        int gy = y0 + ty - 2, gx = x0 + tx - 2;
        float v = 0.f;
        if (gy >= 0 && gy < IMGH && gx >= 0 && gx < IMGW) {
            const float* src = (ci < 3) ? g_x9 : (ci < 6) ? g_x6 : g_x3;
            v = src[(((size_t)b * CH + (ci % 3)) * IMGH + gy) * IMGW + gx];
        }
        s_t[ci][ty][tx] = v;
    }
    __syncthreads();

    float xg = s_red[0];
    #pragma unroll
    for (int w = 1; w < NTHR / 32; w++) xg = fmaxf(xg, s_red[w]);

    const int ty  = threadIdx.y;
    const int tx4 = threadIdx.x * 4;
    const int co  = threadIdx.z;

    float a0 = s_b[co], a1 = a0, a2 = a0, a3 = a0;

    #pragma unroll
    for (int ci = 0; ci < 9; ci++)
        #pragma unroll
        for (int kh = 0; kh < 5; kh++) {
            const float* rowp = &s_t[ci][ty + kh][tx4];
            float4 a = *(const float4*)(rowp);
            float4 c = *(const float4*)(rowp + 4);
            float rb[8] = {a.x, a.y, a.z, a.w, c.x, c.y, c.z, c.w};
            float4 w03 = *(const float4*)&s_w4[co][ci][kh][0];
            float  w4v = s_w4[co][ci][kh][4];
            float wv[5] = {w03.x, w03.y, w03.z, w03.w, w4v};
            #pragma unroll
            for (int kw = 0; kw < 5; kw++) {
                a0 += wv[kw] * rb[kw];
                a1 += wv[kw] * rb[kw + 1];
                a2 += wv[kw] * rb[kw + 2];
                a3 += wv[kw] * rb[kw + 3];
            }
        }

    const int gy = y0 + ty, gx = x0 + tx4;
    size_t idx = (((size_t)b * CH + co) * IMGH + gy) * IMGW + gx;
    float4 xv = *(const float4*)&x[idx];
    float4 r;
    float x0v;
    x0v = fmaxf(a0, 0.f); r.x = fmaxf(xv.x * x0v + (xg - x0v), 0.f);
    x0v = fmaxf(a1, 0.f); r.y = fmaxf(xv.y * x0v + (xg - x0v), 0.f);
    x0v = fmaxf(a2, 0.f); r.z = fmaxf(xv.z * x0v + (xg - x0v), 0.f);
    x0v = fmaxf(a3, 0.f); r.w = fmaxf(xv.w * x0v + (xg - x0v), 0.f);
    *(float4*)&out[idx] = r;
}

// ---------------- launch ----------------------------------------------------
extern "C" void kernel_launch(void* const* d_in, const int* in_sizes, int n_in,
                              void* d_out, int out_size)
{
    (void)in_sizes; (void)n_in; (void)out_size;

    const float* x    = (const float*)d_in[0];
    const float* w3q  = (const float*)d_in[1];
    const float* b3q  = (const float*)d_in[2];
    const float* w3k  = (const float*)d_in[3];
    const float* w3v  = (const float*)d_in[5];
    const float* b3v  = (const float*)d_in[6];
    const float* hw3  = (const float*)d_in[7];
    const float* w6q  = (const float*)d_in[8];
    const float* b6q  = (const float*)d_in[9];
    const float* w6k  = (const float*)d_in[10];
    const float* w6v  = (const float*)d_in[12];
    const float* b6v  = (const float*)d_in[13];
    const float* hw6  = (const float*)d_in[14];
    const float* w9q  = (const float*)d_in[15];
    const float* b9q  = (const float*)d_in[16];
    const float* w9k  = (const float*)d_in[17];
    const float* w9v  = (const float*)d_in[19];
    const float* b9v  = (const float*)d_in[20];
    const float* hw9  = (const float*)d_in[21];
    const float* cw   = (const float*)d_in[22];
    const float* cb   = (const float*)d_in[23];

    float *x3, *x6, *x9;
    cudaGetSymbolAddress((void**)&x3, g_x3);
    cudaGetSymbolAddress((void**)&x6, g_x6);
    cudaGetSymbolAddress((void**)&x9, g_x9);

    // stage p=1: 384x384 windows, 16x16 windows/block, 6 heads fused (+ image max)
    attn1_kernel<16, 16><<<dim3(24, 24, BATCH), 256>>>(x,  x3, w3q, b3q, w3k, w3v, b3v, hw3);
    // stage p=2: 192x192 windows, 8x8 windows/block x 4 head-groups = 256 thr
    attn_split<2, 12, 4, 8, 8><<<dim3(24, 24, BATCH), 256>>>(x3, x6, w6q, b6q, w6k, w6v, b6v, hw6);
    // stage p=3: 128x128 windows, 8x8 windows/block x 2 head-groups = 128 thr
    attn_split<3, 27, 2, 8, 8><<<dim3(16, 16, BATCH), 128>>>(x6, x9, w9q, b9q, w9k, w9v, b9v, hw9);

    final_kernel<<<dim3(IMGW / FOUT_X, IMGH / FOUT_Y, BATCH), dim3(FB_X, FB_Y, 3)>>>(x, cw, cb, (float*)d_out);
}

// round 6
// speedup vs baseline: 1.7134x; 1.0020x over previous
#include <cuda_runtime.h>

// ---------------- problem constants ----------------
#define BATCH 2
#define CH    3
#define IMGH  384
#define IMGW  384
#define IMGPIX (IMGH*IMGW)
#define IMGSZ  (BATCH*CH*IMGPIX)
#define NB1   576   // blocks per batch in the p=1 stage (24*24)

// ---------------- scratch (device globals; no allocations allowed) ----------
__device__ float g_x3[IMGSZ];
__device__ float g_x6[IMGSZ];
__device__ float g_x9[IMGSZ];
__device__ float g_bmax[BATCH*NB1];

// folded weights (written by attn1 blocks (0,0,z), read by attn_split stages)
__device__ float4 g_G6t [4*12*12/4];   // [h][m][n], n padded to DP=12
__device__ float4 g_Wv6t[4*12*12/4];
__device__ float4 g_gb6 [4*12/4];
__device__ float4 g_bv6 [4*12/4];
__device__ float4 g_G9t [2*27*28/4];   // DP=28
__device__ float4 g_Wv9t[2*27*28/4];
__device__ float4 g_gb9 [2*28/4];
__device__ float4 g_bv9 [2*28/4];

__device__ __forceinline__ float neg_inf() { return __int_as_float(0xff800000); }

// ---------------- swizzled shared-tile addressing ---------------------------
template<int P,int TILEH>
__device__ __forceinline__ int sm_idx(int c,int r,int col){
    int sw;
    if (P==1)      sw = col ^ ((r & 1) << 4);
    else if (P==3) sw = col ^ ((r & 3) << 3);
    else {
        int wc = col >> 1;
        int wcs = (wc + (((r >> 1) & 3) << 2)) & 15;
        sw = wcs * 2 + (col & 1);
    }
    return (c * TILEH + r) * 32 + sw;
}
template<int TILEH>
__device__ __forceinline__ int sm_idx2(int c,int r,int wc){ // P==2 float2-word index
    int wcs = (wc + (((r >> 1) & 3) << 2)) & 15;
    return (c * TILEH + r) * 16 + wcs;
}

// ---------------- weight folding (runs inside attn1 on 2 blocks) ------------
__device__ void fold_weights(const float* __restrict__ Wq, const float* __restrict__ bq,
                             const float* __restrict__ Wk,
                             const float* __restrict__ Wv, const float* __restrict__ bv,
                             const float* __restrict__ hw,
                             float* Gt, float* gbp, float* Wvt, float* bvp,
                             int H, int D, int DP, int tid, int nthr)
{
    float scale = rsqrtf((float)D);
    for (int i = tid; i < H * D * DP; i += nthr) {
        int h = i / (D * DP); int r = i % (D * DP); int m = r / DP; int n = r % DP;
        float g = 0.f, wvv = 0.f;
        if (n < D) {
            const float* wk = Wk + h * D * D;
            const float* wq = Wq + h * D * D;
            float s = 0.f;
            for (int e = 0; e < D; e++) s += wk[e * D + n] * wq[e * D + m];
            g   = s * scale;
            wvv = hw[h] * Wv[h * D * D + n * D + m];
        }
        Gt[i] = g; Wvt[i] = wvv;
    }
    for (int i = tid; i < H * DP; i += nthr) {
        int h = i / DP, n = i % DP;
        float gb = 0.f, bvv = 0.f;
        if (n < D) {
            const float* wk = Wk + h * D * D;
            float s = 0.f;
            for (int e = 0; e < D; e++) s += bq[h * D + e] * wk[e * D + n];
            gb  = s * scale;
            bvv = hw[h] * bv[h * D + n];
        }
        gbp[i] = gb; bvp[i] = bvv;
    }
}

// ============================================================================
// p=1 stage: one thread per window, all 6 heads fused (D=3, tiny registers).
// Blocks (0,0,z) additionally fold the p=2 / p=3 weights into global scratch.
// Also computes per-block image max for xg.
// ============================================================================
template<int TW,int TH>
__global__ void __launch_bounds__(TW*TH)
attn1_kernel(const float* __restrict__ in, float* __restrict__ out,
             const float* __restrict__ Wq, const float* __restrict__ bq,
             const float* __restrict__ Wk,
             const float* __restrict__ Wv, const float* __restrict__ bv,
             const float* __restrict__ hw,
             const float* __restrict__ w6q, const float* __restrict__ b6q,
             const float* __restrict__ w6k, const float* __restrict__ w6v,
             const float* __restrict__ b6v, const float* __restrict__ hw6,
             const float* __restrict__ w9q, const float* __restrict__ b9q,
             const float* __restrict__ w9k, const float* __restrict__ w9v,
             const float* __restrict__ b9v, const float* __restrict__ hw9)
{
    constexpr int P = 1, D = 3, HEADS = 6, DP = 4;
    constexpr int NTHR  = TW * TH;
    constexpr int TILEH = TH + 2;
    constexpr int TILEW = TW + 2;

    __shared__ __align__(16) float s_tile[CH * TILEH * 32];
    __shared__ __align__(16) float s_Gt [HEADS * D * DP];
    __shared__ __align__(16) float s_Wvt[HEADS * D * DP];
    __shared__ __align__(16) float s_gbp[HEADS * DP];
    __shared__ __align__(16) float s_bvp[HEADS * DP];
    __shared__ float s_red[NTHR / 32];

    const int tid = threadIdx.x;
    const int b   = blockIdx.z;
    const int wi0 = blockIdx.y * TH;
    const int wj0 = blockIdx.x * TW;
    const float scale = rsqrtf((float)D);

    // blocks (0,0,z) fold the downstream stages' weights into global scratch
    if (blockIdx.x == 0 && blockIdx.y == 0) {
        if (b == 0)
            fold_weights(w6q, b6q, w6k, w6v, b6v, hw6,
                         (float*)g_G6t, (float*)g_gb6, (float*)g_Wv6t, (float*)g_bv6,
                         4, 12, 12, tid, NTHR);
        else
            fold_weights(w9q, b9q, w9k, w9v, b9v, hw9,
                         (float*)g_G9t, (float*)g_gb9, (float*)g_Wv9t, (float*)g_bv9,
                         2, 27, 28, tid, NTHR);
    }

    for (int i = tid; i < HEADS * D * DP; i += NTHR) {
        int h = i / (D * DP); int r = i % (D * DP); int m = r / DP; int n = r % DP;
        float g = 0.f, wvv = 0.f;
        if (n < D) {
            const float* wk = Wk + h * D * D;
            const float* wq = Wq + h * D * D;
            float s = 0.f;
            #pragma unroll
            for (int e = 0; e < D; e++) s += wk[e * D + n] * wq[e * D + m];
            g   = s * scale;
            wvv = hw[h] * Wv[h * D * D + n * D + m];
        }
        s_Gt[i] = g; s_Wvt[i] = wvv;
    }
    for (int i = tid; i < HEADS * DP; i += NTHR) {
        int h = i / DP, n = i % DP;
        float gb = 0.f, bvv = 0.f;
        if (n < D) {
            const float* wk = Wk + h * D * D;
            float s = 0.f;
            #pragma unroll
            for (int e = 0; e < D; e++) s += bq[h * D + e] * wk[e * D + n];
            gb  = s * scale;
            bvv = hw[h] * bv[h * D + n];
        }
        s_gbp[i] = gb; s_bvp[i] = bvv;
    }

    const float* inb = in + (size_t)b * CH * IMGPIX;
    float lmax = neg_inf();
    for (int i = tid; i < CH * TILEH * TILEW; i += NTHR) {
        int c   = i / (TILEH * TILEW);
        int rem = i % (TILEH * TILEW);
        int tr  = rem / TILEW;
        int tc  = rem % TILEW;
        int rr = wi0 - 1 + tr; if (rr < 0) rr = -rr; else if (rr >= IMGH) rr = 2 * IMGH - 2 - rr;
        int cc = wj0 - 1 + tc; if (cc < 0) cc = -cc; else if (cc >= IMGW) cc = 2 * IMGW - 2 - cc;
        float v = inb[c * IMGPIX + rr * IMGW + cc];
        s_tile[sm_idx<P, TILEH>(c, tr, tc)] = v;
        lmax = fmaxf(lmax, v);
    }
    #pragma unroll
    for (int o = 16; o; o >>= 1) lmax = fmaxf(lmax, __shfl_xor_sync(0xffffffffu, lmax, o));
    if ((tid & 31) == 0) s_red[tid >> 5] = lmax;
    __syncthreads();
    if (tid == 0) {
        float m = s_red[0];
        #pragma unroll
        for (int w = 1; w < NTHR / 32; w++) m = fmaxf(m, s_red[w]);
        g_bmax[b * NB1 + blockIdx.y * gridDim.x + blockIdx.x] = m;
    }

    const int lwj = tid % TW;
    const int lwi = tid / TW;

    float tok4[D];
    #pragma unroll
    for (int c = 0; c < CH; c++)
        tok4[c] = s_tile[sm_idx<P, TILEH>(c, lwi + 1, lwj + 1)];

    float u[HEADS][DP];
    #pragma unroll
    for (int h = 0; h < HEADS; h++) {
        float4 v = *(const float4*)&s_gbp[h * DP];
        u[h][0] = v.x; u[h][1] = v.y; u[h][2] = v.z; u[h][3] = v.w;
    }
    #pragma unroll
    for (int h = 0; h < HEADS; h++)
        #pragma unroll
        for (int m = 0; m < D; m++) {
            float4 g = *(const float4*)&s_Gt[(h * D + m) * DP];
            float t = tok4[m];
            u[h][0] += g.x * t; u[h][1] += g.y * t; u[h][2] += g.z * t; u[h][3] += g.w * t;
        }

    float sc[HEADS][9], smax[HEADS];
    #pragma unroll
    for (int h = 0; h < HEADS; h++) smax[h] = neg_inf();

    #pragma unroll
    for (int di = 0; di < 3; di++)
    #pragma unroll
    for (int dj = 0; dj < 3; dj++) {
        float s[HEADS];
        #pragma unroll
        for (int h = 0; h < HEADS; h++) s[h] = 0.f;
        #pragma unroll
        for (int c = 0; c < CH; c++) {
            float v = s_tile[sm_idx<P, TILEH>(c, lwi + di, lwj + dj)];
            #pragma unroll
            for (int h = 0; h < HEADS; h++) s[h] += u[h][c] * v;
        }
        const int t = di * 3 + dj;
        #pragma unroll
        for (int h = 0; h < HEADS; h++) { sc[h][t] = s[h]; smax[h] = fmaxf(smax[h], s[h]); }
    }

    #pragma unroll
    for (int h = 0; h < HEADS; h++) {
        float den = 0.f;
        #pragma unroll
        for (int t = 0; t < 9; t++) { float e = __expf(sc[h][t] - smax[h]); sc[h][t] = e; den += e; }
        float inv = 1.f / den;
        #pragma unroll
        for (int t = 0; t < 9; t++) sc[h][t] *= inv;
    }

    float acc[HEADS][D];
    #pragma unroll
    for (int h = 0; h < HEADS; h++)
        #pragma unroll
        for (int d = 0; d < D; d++) acc[h][d] = 0.f;

    #pragma unroll
    for (int di = 0; di < 3; di++)
    #pragma unroll
    for (int dj = 0; dj < 3; dj++) {
        const int t = di * 3 + dj;
        #pragma unroll
        for (int c = 0; c < CH; c++) {
            float v = s_tile[sm_idx<P, TILEH>(c, lwi + di, lwj + dj)];
            #pragma unroll
            for (int h = 0; h < HEADS; h++) acc[h][c] += sc[h][t] * v;
        }
    }

    float part[DP];
    #pragma unroll
    for (int e = 0; e < DP; e++) part[e] = 0.f;
    #pragma unroll
    for (int h = 0; h < HEADS; h++) {
        float4 bvv = *(const float4*)&s_bvp[h * DP];
        part[0] += bvv.x; part[1] += bvv.y; part[2] += bvv.z; part[3] += bvv.w;
        #pragma unroll
        for (int m = 0; m < D; m++) {
            float4 w = *(const float4*)&s_Wvt[(h * D + m) * DP];
            float a = acc[h][m];
            part[0] += w.x * a; part[1] += w.y * a; part[2] += w.z * a; part[3] += w.w * a;
        }
    }

    float* outb = out + (size_t)b * CH * IMGPIX;
    const int wi = wi0 + lwi, wj = wj0 + lwj;
    #pragma unroll
    for (int c = 0; c < CH; c++)
        outb[c * IMGPIX + wi * IMGW + wj] = part[c];
}

// ============================================================================
// p=2 / p=3 stages: one warp-group per head (h = tid / NW). Folded weights
// read directly from global via warp-uniform float4 loads (L1/L2 resident) —
// no per-block prologue, no weight smem. Head partials combined via
// odd-stride shared scratch.
// ============================================================================
template<int P,int D,int HEADS,int TW,int TH>
__global__ void __launch_bounds__(TW*TH*HEADS)
attn_split(const float* __restrict__ in, float* __restrict__ out,
           const float4* __restrict__ Gt, const float4* __restrict__ gbp,
           const float4* __restrict__ Wvt, const float4* __restrict__ bvp)
{
    constexpr int PP    = P * P;
    constexpr int DP    = (D + 3) & ~3;
    constexpr int DP4   = DP / 4;
    constexpr int DR    = D | 1;            // odd stride for conflict-free scratch
    constexpr int NW    = TW * TH;
    constexpr int NTHR  = NW * HEADS;
    constexpr int TILEH = (TH + 2) * P;
    constexpr int TILEW = (TW + 2) * P;
    static_assert(TILEW <= 32, "tile row must fit padded 32-float row");

    __shared__ __align__(16) float s_tile[CH * TILEH * 32];
    __shared__ float s_part[(HEADS - 1) * NW * DR];

    const int tid = threadIdx.x;
    const int b   = blockIdx.z;
    const int wi0 = blockIdx.y * TH;
    const int wj0 = blockIdx.x * TW;

    const float* inb = in + (size_t)b * CH * IMGPIX;
    for (int i = tid; i < CH * TILEH * TILEW; i += NTHR) {
        int c   = i / (TILEH * TILEW);
        int rem = i % (TILEH * TILEW);
        int tr  = rem / TILEW;
        int tc  = rem % TILEW;
        int rr = (wi0 - 1) * P + tr; if (rr < 0) rr = -rr; else if (rr >= IMGH) rr = 2 * IMGH - 2 - rr;
        int cc = (wj0 - 1) * P + tc; if (cc < 0) cc = -cc; else if (cc >= IMGW) cc = 2 * IMGW - 2 - cc;
        s_tile[sm_idx<P, TILEH>(c, tr, tc)] = inb[c * IMGPIX + rr * IMGW + cc];
    }
    __syncthreads();

    const int w   = tid % NW;
    const int h   = tid / NW;
    const int lwj = w % TW;
    const int lwi = w / TW;

    // ---- center token ----
    float tok4[D];
    if constexpr (P == 2) {
        #pragma unroll
        for (int c = 0; c < CH; c++)
            #pragma unroll
            for (int pi = 0; pi < 2; pi++) {
                float2 v = ((const float2*)s_tile)[sm_idx2<TILEH>(c, (lwi + 1) * 2 + pi, lwj + 1)];
                tok4[c * 4 + pi * 2] = v.x; tok4[c * 4 + pi * 2 + 1] = v.y;
            }
    } else {
        #pragma unroll
        for (int c = 0; c < CH; c++)
            #pragma unroll
            for (int pi = 0; pi < P; pi++)
                #pragma unroll
                for (int pj = 0; pj < P; pj++)
                    tok4[c * PP + pi * P + pj] =
                        s_tile[sm_idx<P, TILEH>(c, (lwi + 1) * P + pi, (lwj + 1) * P + pj)];
    }

    // ---- u = G_h^T tok4 + gb_h (weights via uniform LDG) ----
    float u[DP];
    #pragma unroll
    for (int e4 = 0; e4 < DP4; e4++) {
        float4 v = gbp[h * DP4 + e4];
        u[e4*4] = v.x; u[e4*4+1] = v.y; u[e4*4+2] = v.z; u[e4*4+3] = v.w;
    }
    #pragma unroll
    for (int m = 0; m < D; m++) {
        float t = tok4[m];
        #pragma unroll
        for (int e4 = 0; e4 < DP4; e4++) {
            float4 g = Gt[(h * D + m) * DP4 + e4];
            u[e4*4]   += g.x * t; u[e4*4+1] += g.y * t;
            u[e4*4+2] += g.z * t; u[e4*4+3] += g.w * t;
        }
    }

    // ---- scores ----
    float sc[9];
    float smax = neg_inf();
    #pragma unroll
    for (int di = 0; di < 3; di++)
    #pragma unroll
    for (int dj = 0; dj < 3; dj++) {
        float s = 0.f;
        if constexpr (P == 2) {
            #pragma unroll
            for (int c = 0; c < CH; c++)
                #pragma unroll
                for (int pi = 0; pi < 2; pi++) {
                    float2 v = ((const float2*)s_tile)[sm_idx2<TILEH>(c, (lwi + di) * 2 + pi, lwj + dj)];
                    int e = c * 4 + pi * 2;
                    s += u[e] * v.x + u[e+1] * v.y;
                }
        } else {
            #pragma unroll
            for (int c = 0; c < CH; c++)
                #pragma unroll
                for (int pi = 0; pi < P; pi++)
                    #pragma unroll
                    for (int pj = 0; pj < P; pj++)
                        s += u[c * PP + pi * P + pj] *
                             s_tile[sm_idx<P, TILEH>(c, (lwi + di) * P + pi, (lwj + dj) * P + pj)];
        }
        sc[di * 3 + dj] = s;
        smax = fmaxf(smax, s);
    }

    float den = 0.f;
    #pragma unroll
    for (int t = 0; t < 9; t++) { float e = __expf(sc[t] - smax); sc[t] = e; den += e; }
    float inv = 1.f / den;
    #pragma unroll
    for (int t = 0; t < 9; t++) sc[t] *= inv;

    // ---- weighted token sum ----
    float acc[D];
    #pragma unroll
    for (int d = 0; d < D; d++) acc[d] = 0.f;
    #pragma unroll
    for (int di = 0; di < 3; di++)
    #pragma unroll
    for (int dj = 0; dj < 3; dj++) {
        const float a = sc[di * 3 + dj];
        if constexpr (P == 2) {
            #pragma unroll
            for (int c = 0; c < CH; c++)
                #pragma unroll
                for (int pi = 0; pi < 2; pi++) {
                    float2 v = ((const float2*)s_tile)[sm_idx2<TILEH>(c, (lwi + di) * 2 + pi, lwj + dj)];
                    int e = c * 4 + pi * 2;
                    acc[e] += a * v.x; acc[e+1] += a * v.y;
                }
        } else {
            #pragma unroll
            for (int c = 0; c < CH; c++)
                #pragma unroll
                for (int pi = 0; pi < P; pi++)
                    #pragma unroll
                    for (int pj = 0; pj < P; pj++)
                        acc[c * PP + pi * P + pj] +=
                            a * s_tile[sm_idx<P, TILEH>(c, (lwi + di) * P + pi, (lwj + dj) * P + pj)];
        }
    }

    // ---- projection (hw folded, weights via uniform LDG) ----
    float part[DP];
    #pragma unroll
    for (int e4 = 0; e4 < DP4; e4++) {
        float4 v = bvp[h * DP4 + e4];
        part[e4*4] = v.x; part[e4*4+1] = v.y; part[e4*4+2] = v.z; part[e4*4+3] = v.w;
    }
    #pragma unroll
    for (int m = 0; m < D; m++) {
        float a = acc[m];
        #pragma unroll
        for (int e4 = 0; e4 < DP4; e4++) {
            float4 wv = Wvt[(h * D + m) * DP4 + e4];
            part[e4*4]   += wv.x * a; part[e4*4+1] += wv.y * a;
            part[e4*4+2] += wv.z * a; part[e4*4+3] += wv.w * a;
        }
    }

    // ---- combine heads ----
    if (h > 0) {
        #pragma unroll
        for (int e = 0; e < D; e++)
            s_part[(h - 1) * NW * DR + w * DR + e] = part[e];
    }
    __syncthreads();
    if (h == 0) {
        #pragma unroll
        for (int s = 0; s < HEADS - 1; s++)
            #pragma unroll
            for (int e = 0; e < D; e++)
                part[e] += s_part[s * NW * DR + w * DR + e];

        float* outb = out + (size_t)b * CH * IMGPIX;
        const int wi = wi0 + lwi, wj = wj0 + lwj;
        if constexpr (P == 2) {
            #pragma unroll
            for (int c = 0; c < CH; c++)
                #pragma unroll
                for (int pi = 0; pi < 2; pi++)
                    *(float2*)&outb[c * IMGPIX + (wi * 2 + pi) * IMGW + wj * 2] =
                        make_float2(part[c * 4 + pi * 2], part[c * 4 + pi * 2 + 1]);
        } else {
            #pragma unroll
            for (int c = 0; c < CH; c++)
                #pragma unroll
                for (int pi = 0; pi < P; pi++)
                    #pragma unroll
                    for (int pj = 0; pj < P; pj++)
                        outb[c * IMGPIX + (wi * P + pi) * IMGW + (wj * P + pj)] =
                            part[c * PP + pi * P + pj];
        }
    }
}

// ============================================================================
// fused conv0 (5x5, zero pad 2, cat[x9,x6,x3]) + dehaze epilogue.
// Channel-split: thread (tx,ty,co) computes 4 px of output channel co.
// Smaller tiles (32x8) -> 1152 blocks, more blocks/SM.
// ============================================================================
#define FB_X 8    // threads in x (each does 4 px)
#define FB_Y 8
#define FOUT_X 32
#define FOUT_Y 8

__global__ void __launch_bounds__(FB_X*FB_Y*3)
final_kernel(const float* __restrict__ x,
             const float* __restrict__ conv_w, const float* __restrict__ conv_b,
             float* __restrict__ out)
{
    constexpr int TEH = FOUT_Y + 4, TEW = FOUT_X + 4;   // 12 x 36
    constexpr int NTHR = FB_X * FB_Y * 3;               // 192
    __shared__ __align__(16) float s_t[9][TEH][TEW];
    __shared__ __align__(16) float s_w4[3][9][5][8];    // weight rows padded to 8
    __shared__ float s_b[3];
    __shared__ float s_red[NTHR / 32];

    const int tid = (threadIdx.z * FB_Y + threadIdx.y) * FB_X + threadIdx.x;
    for (int i = tid; i < 675; i += NTHR) {
        int co = i / 225; int r = i % 225; int ci = r / 25; int kk = r % 25;
        s_w4[co][ci][kk / 5][kk % 5] = conv_w[i];
    }
    if (tid < 3) s_b[tid] = conv_b[tid];

    const int b  = blockIdx.z;
    const int y0 = blockIdx.y * FOUT_Y;
    const int x0 = blockIdx.x * FOUT_X;

    // xg = image max (reduced from p=1 per-block maxes)
    float m = neg_inf();
    for (int i = tid; i < NB1; i += NTHR) m = fmaxf(m, g_bmax[b * NB1 + i]);
    #pragma unroll
    for (int o = 16; o; o >>= 1) m = fmaxf(m, __shfl_xor_sync(0xffffffffu, m, o));
    if ((tid & 31) == 0) s_red[tid >> 5] = m;

    for (int i = tid; i < 9 * TEH * TEW; i += NTHR) {
        int ci  = i / (TEH * TEW);
        int rem = i % (TEH * TEW);
        int ty  = rem / TEW;
        int tx  = rem % TEW;
        int gy = y0 + ty - 2, gx = x0 + tx - 2;
        float v = 0.f;
        if (gy >= 0 && gy < IMGH && gx >= 0 && gx < IMGW) {
            const float* src = (ci < 3) ? g_x9 : (ci < 6) ? g_x6 : g_x3;
            v = src[(((size_t)b * CH + (ci % 3)) * IMGH + gy) * IMGW + gx];
        }
        s_t[ci][ty][tx] = v;
    }
    __syncthreads();

    float xg = s_red[0];
    #pragma unroll
    for (int w = 1; w < NTHR / 32; w++) xg = fmaxf(xg, s_red[w]);

    const int ty  = threadIdx.y;
    const int tx4 = threadIdx.x * 4;
    const int co  = threadIdx.z;

    float a0 = s_b[co], a1 = a0, a2 = a0, a3 = a0;

    #pragma unroll
    for (int ci = 0; ci < 9; ci++)
        #pragma unroll
        for (int kh = 0; kh < 5; kh++) {
            const float* rowp = &s_t[ci][ty + kh][tx4];
            float4 a = *(const float4*)(rowp);
            float4 c = *(const float4*)(rowp + 4);
            float rb[8] = {a.x, a.y, a.z, a.w, c.x, c.y, c.z, c.w};
            float4 w03 = *(const float4*)&s_w4[co][ci][kh][0];
            float  w4v = s_w4[co][ci][kh][4];
            float wv[5] = {w03.x, w03.y, w03.z, w03.w, w4v};
            #pragma unroll
            for (int kw = 0; kw < 5; kw++) {
                a0 += wv[kw] * rb[kw];
                a1 += wv[kw] * rb[kw + 1];
                a2 += wv[kw] * rb[kw + 2];
                a3 += wv[kw] * rb[kw + 3];
            }
        }

    const int gy = y0 + ty, gx = x0 + tx4;
    size_t idx = (((size_t)b * CH + co) * IMGH + gy) * IMGW + gx;
    float4 xv = *(const float4*)&x[idx];
    float4 r;
    float x0v;
    x0v = fmaxf(a0, 0.f); r.x = fmaxf(xv.x * x0v + (xg - x0v), 0.f);
    x0v = fmaxf(a1, 0.f); r.y = fmaxf(xv.y * x0v + (xg - x0v), 0.f);
    x0v = fmaxf(a2, 0.f); r.z = fmaxf(xv.z * x0v + (xg - x0v), 0.f);
    x0v = fmaxf(a3, 0.f); r.w = fmaxf(xv.w * x0v + (xg - x0v), 0.f);
    *(float4*)&out[idx] = r;
}

// ---------------- launch ----------------------------------------------------
extern "C" void kernel_launch(void* const* d_in, const int* in_sizes, int n_in,
                              void* d_out, int out_size)
{
    (void)in_sizes; (void)n_in; (void)out_size;

    const float* x    = (const float*)d_in[0];
    const float* w3q  = (const float*)d_in[1];
    const float* b3q  = (const float*)d_in[2];
    const float* w3k  = (const float*)d_in[3];
    const float* w3v  = (const float*)d_in[5];
    const float* b3v  = (const float*)d_in[6];
    const float* hw3  = (const float*)d_in[7];
    const float* w6q  = (const float*)d_in[8];
    const float* b6q  = (const float*)d_in[9];
    const float* w6k  = (const float*)d_in[10];
    const float* w6v  = (const float*)d_in[12];
    const float* b6v  = (const float*)d_in[13];
    const float* hw6  = (const float*)d_in[14];
    const float* w9q  = (const float*)d_in[15];
    const float* b9q  = (const float*)d_in[16];
    const float* w9k  = (const float*)d_in[17];
    const float* w9v  = (const float*)d_in[19];
    const float* b9v  = (const float*)d_in[20];
    const float* hw9  = (const float*)d_in[21];
    const float* cw   = (const float*)d_in[22];
    const float* cb   = (const float*)d_in[23];

    float *x3, *x6, *x9;
    cudaGetSymbolAddress((void**)&x3, g_x3);
    cudaGetSymbolAddress((void**)&x6, g_x6);
    cudaGetSymbolAddress((void**)&x9, g_x9);
    float4 *G6, *gb6, *Wv6, *bv6, *G9, *gb9, *Wv9, *bv9;
    cudaGetSymbolAddress((void**)&G6,  g_G6t);
    cudaGetSymbolAddress((void**)&gb6, g_gb6);
    cudaGetSymbolAddress((void**)&Wv6, g_Wv6t);
    cudaGetSymbolAddress((void**)&bv6, g_bv6);
    cudaGetSymbolAddress((void**)&G9,  g_G9t);
    cudaGetSymbolAddress((void**)&gb9, g_gb9);
    cudaGetSymbolAddress((void**)&Wv9, g_Wv9t);
    cudaGetSymbolAddress((void**)&bv9, g_bv9);

    // stage p=1: 384x384 windows, 16x16 windows/block, 6 heads fused
    // (+ image max, + weight folding for the later stages on blocks (0,0,z))
    attn1_kernel<16, 16><<<dim3(24, 24, BATCH), 256>>>(
        x, x3, w3q, b3q, w3k, w3v, b3v, hw3,
        w6q, b6q, w6k, w6v, b6v, hw6,
        w9q, b9q, w9k, w9v, b9v, hw9);
    // stage p=2: 192x192 windows, 8x8 windows/block x 4 head-groups = 256 thr
    attn_split<2, 12, 4, 8, 8><<<dim3(24, 24, BATCH), 256>>>(x3, x6, G6, gb6, Wv6, bv6);
    // stage p=3: 128x128 windows, 8x8 windows/block x 2 head-groups = 128 thr
    attn_split<3, 27, 2, 8, 8><<<dim3(16, 16, BATCH), 128>>>(x6, x9, G9, gb9, Wv9, bv9);

    final_kernel<<<dim3(IMGW / FOUT_X, IMGH / FOUT_Y, BATCH), dim3(FB_X, FB_Y, 3)>>>(x, cw, cb, (float*)d_out);
}

// round 7
// speedup vs baseline: 2.0385x; 1.1898x over previous
#include <cuda_runtime.h>

// ---------------- problem constants ----------------
#define BATCH 2
#define CH    3
#define IMGH  384
#define IMGW  384
#define IMGPIX (IMGH*IMGW)
#define IMGSZ  (BATCH*CH*IMGPIX)
#define NB1   576   // blocks per batch in the p=1 stage (24*24)

// ---------------- scratch (device globals; no allocations allowed) ----------
__device__ float g_x3[IMGSZ];
__device__ float g_x6[IMGSZ];
__device__ float g_x9[IMGSZ];
__device__ float g_bmax[BATCH*NB1];

// folded weights (written by attn1 blocks (0,0,z), read by attn_split stages)
__device__ float4 g_G6t [4*12*12/4];   // [h][m][n], n padded to DP=12
__device__ float4 g_Wv6t[4*12*12/4];
__device__ float4 g_gb6 [4*12/4];
__device__ float4 g_bv6 [4*12/4];
__device__ float4 g_G9t [2*27*28/4];   // DP=28
__device__ float4 g_Wv9t[2*27*28/4];
__device__ float4 g_gb9 [2*28/4];
__device__ float4 g_bv9 [2*28/4];

__device__ __forceinline__ float neg_inf() { return __int_as_float(0xff800000); }

__device__ __forceinline__ int reflect_h(int r) {
    if (r < 0) r = -r; else if (r >= IMGH) r = 2 * IMGH - 2 - r; return r;
}
__device__ __forceinline__ int reflect_w(int c) {
    if (c < 0) c = -c; else if (c >= IMGW) c = 2 * IMGW - 2 - c; return c;
}

// ---------------- weight folding (runs inside attn1 on 2 blocks) ------------
__device__ void fold_weights(const float* __restrict__ Wq, const float* __restrict__ bq,
                             const float* __restrict__ Wk,
                             const float* __restrict__ Wv, const float* __restrict__ bv,
                             const float* __restrict__ hw,
                             float* Gt, float* gbp, float* Wvt, float* bvp,
                             int H, int D, int DP, int tid, int nthr)
{
    float scale = rsqrtf((float)D);
    for (int i = tid; i < H * D * DP; i += nthr) {
        int h = i / (D * DP); int r = i % (D * DP); int m = r / DP; int n = r % DP;
        float g = 0.f, wvv = 0.f;
        if (n < D) {
            const float* wk = Wk + h * D * D;
            const float* wq = Wq + h * D * D;
            float s = 0.f;
            for (int e = 0; e < D; e++) s += wk[e * D + n] * wq[e * D + m];
            g   = s * scale;
            wvv = hw[h] * Wv[h * D * D + n * D + m];
        }
        Gt[i] = g; Wvt[i] = wvv;
    }
    for (int i = tid; i < H * DP; i += nthr) {
        int h = i / DP, n = i % DP;
        float gb = 0.f, bvv = 0.f;
        if (n < D) {
            const float* wk = Wk + h * D * D;
            float s = 0.f;
            for (int e = 0; e < D; e++) s += bq[h * D + e] * wk[e * D + n];
            gb  = s * scale;
            bvv = hw[h] * bv[h * D + n];
        }
        gbp[i] = gb; bvp[i] = bvv;
    }
}

// ============================================================================
// p=1 stage: one thread per window, all 6 heads fused. Channel-interleaved
// float4 tile (pixel -> {c0,c1,c2,pad}) => 1 LDS.128 per token read.
// Blocks (0,0,z) also fold p=2/p=3 weights. Computes per-block image max.
// ============================================================================
#define A1_TW 16
#define A1_TH 16
__global__ void __launch_bounds__(A1_TW*A1_TH)
attn1_kernel(const float* __restrict__ in, float* __restrict__ out,
             const float* __restrict__ Wq, const float* __restrict__ bq,
             const float* __restrict__ Wk,
             const float* __restrict__ Wv, const float* __restrict__ bv,
             const float* __restrict__ hw,
             const float* __restrict__ w6q, const float* __restrict__ b6q,
             const float* __restrict__ w6k, const float* __restrict__ w6v,
             const float* __restrict__ b6v, const float* __restrict__ hw6,
             const float* __restrict__ w9q, const float* __restrict__ b9q,
             const float* __restrict__ w9k, const float* __restrict__ w9v,
             const float* __restrict__ b9v, const float* __restrict__ hw9)
{
    constexpr int D = 3, HEADS = 6, DP = 4;
    constexpr int NTHR  = A1_TW * A1_TH;          // 256
    constexpr int TILEH = A1_TH + 2;              // 18
    constexpr int TILEW = A1_TW + 2;              // 18
    constexpr int ELEMS = TILEH * TILEW;          // 324

    __shared__ __align__(16) float4 s_t4[TILEH * TILEW];
    __shared__ __align__(16) float s_Gt [HEADS * D * DP];
    __shared__ __align__(16) float s_Wvt[HEADS * D * DP];
    __shared__ __align__(16) float s_gbp[HEADS * DP];
    __shared__ __align__(16) float s_bvp[HEADS * DP];
    __shared__ float s_red[NTHR / 32];

    const int tid = threadIdx.x;
    const int b   = blockIdx.z;
    const int wi0 = blockIdx.y * A1_TH;
    const int wj0 = blockIdx.x * A1_TW;
    const float scale = rsqrtf((float)D);

    if (blockIdx.x == 0 && blockIdx.y == 0) {
        if (b == 0)
            fold_weights(w6q, b6q, w6k, w6v, b6v, hw6,
                         (float*)g_G6t, (float*)g_gb6, (float*)g_Wv6t, (float*)g_bv6,
                         4, 12, 12, tid, NTHR);
        else
            fold_weights(w9q, b9q, w9k, w9v, b9v, hw9,
                         (float*)g_G9t, (float*)g_gb9, (float*)g_Wv9t, (float*)g_bv9,
                         2, 27, 28, tid, NTHR);
    }

    for (int i = tid; i < HEADS * D * DP; i += NTHR) {
        int h = i / (D * DP); int r = i % (D * DP); int m = r / DP; int n = r % DP;
        float g = 0.f, wvv = 0.f;
        if (n < D) {
            const float* wk = Wk + h * D * D;
            const float* wq = Wq + h * D * D;
            float s = 0.f;
            #pragma unroll
            for (int e = 0; e < D; e++) s += wk[e * D + n] * wq[e * D + m];
            g   = s * scale;
            wvv = hw[h] * Wv[h * D * D + n * D + m];
        }
        s_Gt[i] = g; s_Wvt[i] = wvv;
    }
    for (int i = tid; i < HEADS * DP; i += NTHR) {
        int h = i / DP, n = i % DP;
        float gb = 0.f, bvv = 0.f;
        if (n < D) {
            const float* wk = Wk + h * D * D;
            float s = 0.f;
            #pragma unroll
            for (int e = 0; e < D; e++) s += bq[h * D + e] * wk[e * D + n];
            gb  = s * scale;
            bvv = hw[h] * bv[h * D + n];
        }
        s_gbp[i] = gb; s_bvp[i] = bvv;
    }

    // ---- tile load: per-thread indices hoisted out of the channel loop ----
    const float* inb = in + (size_t)b * CH * IMGPIX;
    float lmax = neg_inf();
    {
        // k=0: i=tid (always <324); k=1: i=tid+256 (<324 iff tid<68)
        int i0 = tid;
        int tr0 = i0 / TILEW, tc0 = i0 % TILEW;
        int off0 = reflect_h(wi0 - 1 + tr0) * IMGW + reflect_w(wj0 - 1 + tc0);
        int i1 = tid + NTHR;
        int tr1 = i1 / TILEW, tc1 = i1 % TILEW;
        bool v1 = (i1 < ELEMS);
        int off1 = v1 ? reflect_h(wi0 - 1 + tr1) * IMGW + reflect_w(wj0 - 1 + tc1) : 0;

        float4 p0, p1;
        float a;
        a = inb[0 * IMGPIX + off0]; p0.x = a; lmax = fmaxf(lmax, a);
        a = inb[1 * IMGPIX + off0]; p0.y = a; lmax = fmaxf(lmax, a);
        a = inb[2 * IMGPIX + off0]; p0.z = a; lmax = fmaxf(lmax, a);
        p0.w = 0.f;
        s_t4[i0] = p0;
        if (v1) {
            a = inb[0 * IMGPIX + off1]; p1.x = a; lmax = fmaxf(lmax, a);
            a = inb[1 * IMGPIX + off1]; p1.y = a; lmax = fmaxf(lmax, a);
            a = inb[2 * IMGPIX + off1]; p1.z = a; lmax = fmaxf(lmax, a);
            p1.w = 0.f;
            s_t4[i1] = p1;
        }
    }
    #pragma unroll
    for (int o = 16; o; o >>= 1) lmax = fmaxf(lmax, __shfl_xor_sync(0xffffffffu, lmax, o));
    if ((tid & 31) == 0) s_red[tid >> 5] = lmax;
    __syncthreads();
    if (tid == 0) {
        float m = s_red[0];
        #pragma unroll
        for (int w = 1; w < NTHR / 32; w++) m = fmaxf(m, s_red[w]);
        g_bmax[b * NB1 + blockIdx.y * gridDim.x + blockIdx.x] = m;
    }

    const int lwj = tid % A1_TW;
    const int lwi = tid / A1_TW;

    float4 t4 = s_t4[(lwi + 1) * TILEW + (lwj + 1)];
    float tok4[D] = {t4.x, t4.y, t4.z};

    float u[HEADS][DP];
    #pragma unroll
    for (int h = 0; h < HEADS; h++) {
        float4 v = *(const float4*)&s_gbp[h * DP];
        u[h][0] = v.x; u[h][1] = v.y; u[h][2] = v.z; u[h][3] = v.w;
    }
    #pragma unroll
    for (int h = 0; h < HEADS; h++)
        #pragma unroll
        for (int m = 0; m < D; m++) {
            float4 g = *(const float4*)&s_Gt[(h * D + m) * DP];
            float t = tok4[m];
            u[h][0] += g.x * t; u[h][1] += g.y * t; u[h][2] += g.z * t; u[h][3] += g.w * t;
        }

    float sc[HEADS][9], smax[HEADS];
    #pragma unroll
    for (int h = 0; h < HEADS; h++) smax[h] = neg_inf();

    #pragma unroll
    for (int di = 0; di < 3; di++)
    #pragma unroll
    for (int dj = 0; dj < 3; dj++) {
        float4 v = s_t4[(lwi + di) * TILEW + (lwj + dj)];
        const int t = di * 3 + dj;
        #pragma unroll
        for (int h = 0; h < HEADS; h++) {
            float s = u[h][0] * v.x + u[h][1] * v.y + u[h][2] * v.z;
            sc[h][t] = s; smax[h] = fmaxf(smax[h], s);
        }
    }

    #pragma unroll
    for (int h = 0; h < HEADS; h++) {
        float den = 0.f;
        #pragma unroll
        for (int t = 0; t < 9; t++) { float e = __expf(sc[h][t] - smax[h]); sc[h][t] = e; den += e; }
        float inv = 1.f / den;
        #pragma unroll
        for (int t = 0; t < 9; t++) sc[h][t] *= inv;
    }

    float acc[HEADS][D];
    #pragma unroll
    for (int h = 0; h < HEADS; h++)
        #pragma unroll
        for (int d = 0; d < D; d++) acc[h][d] = 0.f;

    #pragma unroll
    for (int di = 0; di < 3; di++)
    #pragma unroll
    for (int dj = 0; dj < 3; dj++) {
        float4 v = s_t4[(lwi + di) * TILEW + (lwj + dj)];
        const int t = di * 3 + dj;
        #pragma unroll
        for (int h = 0; h < HEADS; h++) {
            acc[h][0] += sc[h][t] * v.x;
            acc[h][1] += sc[h][t] * v.y;
            acc[h][2] += sc[h][t] * v.z;
        }
    }

    float part[DP];
    #pragma unroll
    for (int e = 0; e < DP; e++) part[e] = 0.f;
    #pragma unroll
    for (int h = 0; h < HEADS; h++) {
        float4 bvv = *(const float4*)&s_bvp[h * DP];
        part[0] += bvv.x; part[1] += bvv.y; part[2] += bvv.z; part[3] += bvv.w;
        #pragma unroll
        for (int m = 0; m < D; m++) {
            float4 w = *(const float4*)&s_Wvt[(h * D + m) * DP];
            float a = acc[h][m];
            part[0] += w.x * a; part[1] += w.y * a; part[2] += w.z * a; part[3] += w.w * a;
        }
    }

    float* outb = out + (size_t)b * CH * IMGPIX;
    const int wi = wi0 + lwi, wj = wj0 + lwj;
    #pragma unroll
    for (int c = 0; c < CH; c++)
        outb[c * IMGPIX + wi * IMGW + wj] = part[c];
}

// ============================================================================
// p=2 stage: one warp-group per head; float2-word rotated tile (as before),
// load indices hoisted. Folded weights via uniform LDG.
// ============================================================================
template<int TILEH>
__device__ __forceinline__ int sm_idx2w(int c,int r,int wc){ // float2-word index
    int wcs = (wc + (((r >> 1) & 3) << 2)) & 15;
    return (c * TILEH + r) * 16 + wcs;
}

#define A2_TW 8
#define A2_TH 8
__global__ void __launch_bounds__(A2_TW*A2_TH*4)
attn2_kernel(const float* __restrict__ in, float* __restrict__ out,
             const float4* __restrict__ Gt, const float4* __restrict__ gbp,
             const float4* __restrict__ Wvt, const float4* __restrict__ bvp)
{
    constexpr int P = 2, D = 12, HEADS = 4;
    constexpr int DP = 12, DP4 = 3;
    constexpr int DR = 13;
    constexpr int NW = A2_TW * A2_TH;          // 64
    constexpr int NTHR = NW * HEADS;           // 256
    constexpr int TILEH = (A2_TH + 2) * P;     // 20
    constexpr int TILEW = (A2_TW + 2) * P;     // 20
    constexpr int ELEMS = TILEH * TILEW;       // 400

    __shared__ __align__(16) float s_tile[CH * TILEH * 32];
    __shared__ float s_part[(HEADS - 1) * NW * DR];

    const int tid = threadIdx.x;
    const int b   = blockIdx.z;
    const int wi0 = blockIdx.y * A2_TH;
    const int wj0 = blockIdx.x * A2_TW;

    const float* inb = in + (size_t)b * CH * IMGPIX;
    {
        int i0 = tid;
        int tr0 = i0 / TILEW, tc0 = i0 % TILEW;
        int off0 = reflect_h((wi0 - 1) * P + tr0) * IMGW + reflect_w((wj0 - 1) * P + tc0);
        int sm0  = sm_idx2w<TILEH>(0, tr0, tc0 >> 1) * 2 + (tc0 & 1);
        int i1 = tid + NTHR;
        bool v1 = (i1 < ELEMS);
        int tr1 = i1 / TILEW, tc1 = i1 % TILEW;
        int off1 = 0, sm1 = 0;
        if (v1) {
            off1 = reflect_h((wi0 - 1) * P + tr1) * IMGW + reflect_w((wj0 - 1) * P + tc1);
            sm1  = sm_idx2w<TILEH>(0, tr1, tc1 >> 1) * 2 + (tc1 & 1);
        }
        #pragma unroll
        for (int c = 0; c < CH; c++) {
            s_tile[c * TILEH * 32 + sm0] = inb[c * IMGPIX + off0];
            if (v1) s_tile[c * TILEH * 32 + sm1] = inb[c * IMGPIX + off1];
        }
    }
    __syncthreads();

    const int w   = tid % NW;
    const int h   = tid / NW;
    const int lwj = w % A2_TW;
    const int lwi = w / A2_TW;

    float tok4[D];
    #pragma unroll
    for (int c = 0; c < CH; c++)
        #pragma unroll
        for (int pi = 0; pi < 2; pi++) {
            float2 v = ((const float2*)s_tile)[sm_idx2w<TILEH>(c, (lwi + 1) * 2 + pi, lwj + 1)];
            tok4[c * 4 + pi * 2] = v.x; tok4[c * 4 + pi * 2 + 1] = v.y;
        }

    float u[DP];
    #pragma unroll
    for (int e4 = 0; e4 < DP4; e4++) {
        float4 v = gbp[h * DP4 + e4];
        u[e4*4] = v.x; u[e4*4+1] = v.y; u[e4*4+2] = v.z; u[e4*4+3] = v.w;
    }
    #pragma unroll
    for (int m = 0; m < D; m++) {
        float t = tok4[m];
        #pragma unroll
        for (int e4 = 0; e4 < DP4; e4++) {
            float4 g = Gt[(h * D + m) * DP4 + e4];
            u[e4*4]   += g.x * t; u[e4*4+1] += g.y * t;
            u[e4*4+2] += g.z * t; u[e4*4+3] += g.w * t;
        }
    }

    float sc[9];
    float smax = neg_inf();
    #pragma unroll
    for (int di = 0; di < 3; di++)
    #pragma unroll
    for (int dj = 0; dj < 3; dj++) {
        float s = 0.f;
        #pragma unroll
        for (int c = 0; c < CH; c++)
            #pragma unroll
            for (int pi = 0; pi < 2; pi++) {
                float2 v = ((const float2*)s_tile)[sm_idx2w<TILEH>(c, (lwi + di) * 2 + pi, lwj + dj)];
                int e = c * 4 + pi * 2;
                s += u[e] * v.x + u[e+1] * v.y;
            }
        sc[di * 3 + dj] = s;
        smax = fmaxf(smax, s);
    }

    float den = 0.f;
    #pragma unroll
    for (int t = 0; t < 9; t++) { float e = __expf(sc[t] - smax); sc[t] = e; den += e; }
    float inv = 1.f / den;
    #pragma unroll
    for (int t = 0; t < 9; t++) sc[t] *= inv;

    float acc[D];
    #pragma unroll
    for (int d = 0; d < D; d++) acc[d] = 0.f;
    #pragma unroll
    for (int di = 0; di < 3; di++)
    #pragma unroll
    for (int dj = 0; dj < 3; dj++) {
        const float a = sc[di * 3 + dj];
        #pragma unroll
        for (int c = 0; c < CH; c++)
            #pragma unroll
            for (int pi = 0; pi < 2; pi++) {
                float2 v = ((const float2*)s_tile)[sm_idx2w<TILEH>(c, (lwi + di) * 2 + pi, lwj + dj)];
                int e = c * 4 + pi * 2;
                acc[e] += a * v.x; acc[e+1] += a * v.y;
            }
    }

    float part[DP];
    #pragma unroll
    for (int e4 = 0; e4 < DP4; e4++) {
        float4 v = bvp[h * DP4 + e4];
        part[e4*4] = v.x; part[e4*4+1] = v.y; part[e4*4+2] = v.z; part[e4*4+3] = v.w;
    }
    #pragma unroll
    for (int m = 0; m < D; m++) {
        float a = acc[m];
        #pragma unroll
        for (int e4 = 0; e4 < DP4; e4++) {
            float4 wv = Wvt[(h * D + m) * DP4 + e4];
            part[e4*4]   += wv.x * a; part[e4*4+1] += wv.y * a;
            part[e4*4+2] += wv.z * a; part[e4*4+3] += wv.w * a;
        }
    }

    if (h > 0) {
        #pragma unroll
        for (int e = 0; e < D; e++)
            s_part[(h - 1) * NW * DR + w * DR + e] = part[e];
    }
    __syncthreads();
    if (h == 0) {
        #pragma unroll
        for (int s = 0; s < HEADS - 1; s++)
            #pragma unroll
            for (int e = 0; e < D; e++)
                part[e] += s_part[s * NW * DR + w * DR + e];

        float* outb = out + (size_t)b * CH * IMGPIX;
        const int wi = wi0 + lwi, wj = wj0 + lwj;
        #pragma unroll
        for (int c = 0; c < CH; c++)
            #pragma unroll
            for (int pi = 0; pi < 2; pi++)
                *(float2*)&outb[c * IMGPIX + (wi * 2 + pi) * IMGW + wj * 2] =
                    make_float2(part[c * 4 + pi * 2], part[c * 4 + pi * 2 + 1]);
    }
}

// ============================================================================
// p=3 stage: one warp-group per head. Window rows padded to 4 floats -> every
// token row is one conflict-free LDS.128. Load indices hoisted over channels.
// ============================================================================
#define A3_TW 8
#define A3_TH 8
__global__ void __launch_bounds__(A3_TW*A3_TH*2)
attn3_kernel(const float* __restrict__ in, float* __restrict__ out,
             const float4* __restrict__ Gt, const float4* __restrict__ gbp,
             const float4* __restrict__ Wvt, const float4* __restrict__ bvp)
{
    constexpr int D = 27, HEADS = 2;
    constexpr int DP = 28, DP4 = 7;
    constexpr int DR = 27;                      // odd
    constexpr int NW = A3_TW * A3_TH;           // 64
    constexpr int NTHR = NW * HEADS;            // 128
    constexpr int TILEH = (A3_TH + 2) * 3;      // 30
    constexpr int ROWW4 = 12;                   // 10 windows * 4 floats = 40, pad to 48 floats = 12 float4
    constexpr int ELEMS = TILEH * 30;           // 900 image pixels per channel
    constexpr int ITERS = 8;                    // ceil(900/128); last partial (tid<4)

    __shared__ __align__(16) float4 s_t4[CH * TILEH * ROWW4];
    __shared__ float s_part[(HEADS - 1) * NW * DR];

    const int tid = threadIdx.x;
    const int b   = blockIdx.z;
    const int wi0 = blockIdx.y * A3_TH;
    const int wj0 = blockIdx.x * A3_TW;

    const float* inb = in + (size_t)b * CH * IMGPIX;
    float* s_tf = (float*)s_t4;
    {
        int offs[ITERS], sms[ITERS];
        #pragma unroll
        for (int k = 0; k < ITERS; k++) {
            int i = tid + k * NTHR;
            if (k == ITERS - 1 && i >= ELEMS) { offs[k] = -1; continue; }
            int tr = i / 30, tc = i % 30;
            offs[k] = reflect_h((wi0 - 1) * 3 + tr) * IMGW + reflect_w((wj0 - 1) * 3 + tc);
            sms[k]  = tr * (ROWW4 * 4) + (tc / 3) * 4 + tc % 3;
        }
        #pragma unroll
        for (int c = 0; c < CH; c++)
            #pragma unroll
            for (int k = 0; k < ITERS; k++) {
                if (k == ITERS - 1 && offs[k] < 0) continue;
                s_tf[c * TILEH * ROWW4 * 4 + sms[k]] = inb[c * IMGPIX + offs[k]];
            }
    }
    __syncthreads();

    const int w   = tid % NW;
    const int h   = tid / NW;
    const int lwj = w % A3_TW;
    const int lwi = w / A3_TW;

    // ---- center token (float4 rows) ----
    float tok4[D];
    #pragma unroll
    for (int c = 0; c < CH; c++)
        #pragma unroll
        for (int pi = 0; pi < 3; pi++) {
            float4 v = s_t4[(c * TILEH + (lwi + 1) * 3 + pi) * ROWW4 + (lwj + 1)];
            int e = c * 9 + pi * 3;
            tok4[e] = v.x; tok4[e+1] = v.y; tok4[e+2] = v.z;
        }

    // ---- u = G_h^T tok4 + gb_h (weights via uniform LDG) ----
    float u[DP];
    #pragma unroll
    for (int e4 = 0; e4 < DP4; e4++) {
        float4 v = gbp[h * DP4 + e4];
        u[e4*4] = v.x; u[e4*4+1] = v.y; u[e4*4+2] = v.z; u[e4*4+3] = v.w;
    }
    #pragma unroll
    for (int m = 0; m < D; m++) {
        float t = tok4[m];
        #pragma unroll
        for (int e4 = 0; e4 < DP4; e4++) {
            float4 g = Gt[(h * D + m) * DP4 + e4];
            u[e4*4]   += g.x * t; u[e4*4+1] += g.y * t;
            u[e4*4+2] += g.z * t; u[e4*4+3] += g.w * t;
        }
    }

    // ---- scores (float4 token rows) ----
    float sc[9];
    float smax = neg_inf();
    #pragma unroll
    for (int di = 0; di < 3; di++)
    #pragma unroll
    for (int dj = 0; dj < 3; dj++) {
        float s = 0.f;
        #pragma unroll
        for (int c = 0; c < CH; c++)
            #pragma unroll
            for (int pi = 0; pi < 3; pi++) {
                float4 v = s_t4[(c * TILEH + (lwi + di) * 3 + pi) * ROWW4 + (lwj + dj)];
                int e = c * 9 + pi * 3;
                s += u[e] * v.x + u[e+1] * v.y + u[e+2] * v.z;
            }
        sc[di * 3 + dj] = s;
        smax = fmaxf(smax, s);
    }

    float den = 0.f;
    #pragma unroll
    for (int t = 0; t < 9; t++) { float e = __expf(sc[t] - smax); sc[t] = e; den += e; }
    float inv = 1.f / den;
    #pragma unroll
    for (int t = 0; t < 9; t++) sc[t] *= inv;

    // ---- weighted token sum ----
    float acc[D];
    #pragma unroll
    for (int d = 0; d < D; d++) acc[d] = 0.f;
    #pragma unroll
    for (int di = 0; di < 3; di++)
    #pragma unroll
    for (int dj = 0; dj < 3; dj++) {
        const float a = sc[di * 3 + dj];
        #pragma unroll
        for (int c = 0; c < CH; c++)
            #pragma unroll
            for (int pi = 0; pi < 3; pi++) {
                float4 v = s_t4[(c * TILEH + (lwi + di) * 3 + pi) * ROWW4 + (lwj + dj)];
                int e = c * 9 + pi * 3;
                acc[e] += a * v.x; acc[e+1] += a * v.y; acc[e+2] += a * v.z;
            }
    }

    // ---- projection (hw folded, weights via uniform LDG) ----
    float part[DP];
    #pragma unroll
    for (int e4 = 0; e4 < DP4; e4++) {
        float4 v = bvp[h * DP4 + e4];
        part[e4*4] = v.x; part[e4*4+1] = v.y; part[e4*4+2] = v.z; part[e4*4+3] = v.w;
    }
    #pragma unroll
    for (int m = 0; m < D; m++) {
        float a = acc[m];
        #pragma unroll
        for (int e4 = 0; e4 < DP4; e4++) {
            float4 wv = Wvt[(h * D + m) * DP4 + e4];
            part[e4*4]   += wv.x * a; part[e4*4+1] += wv.y * a;
            part[e4*4+2] += wv.z * a; part[e4*4+3] += wv.w * a;
        }
    }

    if (h > 0) {
        #pragma unroll
        for (int e = 0; e < D; e++)
            s_part[(h - 1) * NW * DR + w * DR + e] = part[e];
    }
    __syncthreads();
    if (h == 0) {
        #pragma unroll
        for (int s = 0; s < HEADS - 1; s++)
            #pragma unroll
            for (int e = 0; e < D; e++)
                part[e] += s_part[s * NW * DR + w * DR + e];

        float* outb = out + (size_t)b * CH * IMGPIX;
        const int wi = wi0 + lwi, wj = wj0 + lwj;
        #pragma unroll
        for (int c = 0; c < CH; c++)
            #pragma unroll
            for (int pi = 0; pi < 3; pi++)
                #pragma unroll
                for (int pj = 0; pj < 3; pj++)
                    outb[c * IMGPIX + (wi * 3 + pi) * IMGW + (wj * 3 + pj)] =
                        part[c * 9 + pi * 3 + pj];
    }
}

// ============================================================================
// fused conv0 (5x5, zero pad 2, cat[x9,x6,x3]) + dehaze epilogue.
// 32x16 tile, channel-split across threadIdx.z (384 threads).
// Tile load: per-thread indices hoisted, ci-outer unrolled (constant src).
// ============================================================================
#define FB_X 8    // threads in x (each does 4 px)
#define FB_Y 16
#define FOUT_X 32
#define FOUT_Y 16

__global__ void __launch_bounds__(FB_X*FB_Y*3)
final_kernel(const float* __restrict__ x,
             const float* __restrict__ conv_w, const float* __restrict__ conv_b,
             float* __restrict__ out)
{
    constexpr int TEH = FOUT_Y + 4, TEW = FOUT_X + 4;   // 20 x 36
    constexpr int NTHR = FB_X * FB_Y * 3;               // 384
    constexpr int CELEM = TEH * TEW;                    // 720 per channel
    __shared__ __align__(16) float s_t[9][TEH][TEW];
    __shared__ __align__(16) float s_w4[3][9][5][8];    // weight rows padded to 8
    __shared__ float s_b[3];
    __shared__ float s_red[NTHR / 32];

    const int tid = (threadIdx.z * FB_Y + threadIdx.y) * FB_X + threadIdx.x;
    for (int i = tid; i < 675; i += NTHR) {
        int co = i / 225; int r = i % 225; int ci = r / 25; int kk = r % 25;
        s_w4[co][ci][kk / 5][kk % 5] = conv_w[i];
    }
    if (tid < 3) s_b[tid] = conv_b[tid];

    const int b  = blockIdx.z;
    const int y0 = blockIdx.y * FOUT_Y;
    const int x0 = blockIdx.x * FOUT_X;

    // xg = image max (reduced from p=1 per-block maxes)
    float m = neg_inf();
    for (int i = tid; i < NB1; i += NTHR) m = fmaxf(m, g_bmax[b * NB1 + i]);
    #pragma unroll
    for (int o = 16; o; o >>= 1) m = fmaxf(m, __shfl_xor_sync(0xffffffffu, m, o));
    if ((tid & 31) == 0) s_red[tid >> 5] = m;

    // ---- halo tile load: indices hoisted, ci-outer (src resolved at compile time)
    {
        int j0 = tid;                 // < 720 always
        int ty0 = j0 / TEW, tx0 = j0 % TEW;
        int gy0 = y0 + ty0 - 2, gx0 = x0 + tx0 - 2;
        bool v0 = (gy0 >= 0 && gy0 < IMGH && gx0 >= 0 && gx0 < IMGW);
        int off0 = v0 ? gy0 * IMGW + gx0 : 0;

        int j1 = tid + NTHR;          // < 720 iff tid < 336
        bool in1 = (j1 < CELEM);
        int ty1 = j1 / TEW, tx1 = j1 % TEW;
        int gy1 = y0 + ty1 - 2, gx1 = x0 + tx1 - 2;
        bool v1 = in1 && (gy1 >= 0 && gy1 < IMGH && gx1 >= 0 && gx1 < IMGW);
        int off1 = v1 ? gy1 * IMGW + gx1 : 0;

        #pragma unroll
        for (int ci = 0; ci < 9; ci++) {
            const float* src = (ci < 3) ? g_x9 : (ci < 6) ? g_x6 : g_x3;
            const float* base = src + ((size_t)b * CH + (ci % 3)) * IMGPIX;
            (&s_t[ci][0][0])[j0] = v0 ? base[off0] : 0.f;
            if (in1) (&s_t[ci][0][0])[j1] = v1 ? base[off1] : 0.f;
        }
    }
    __syncthreads();

    float xg = s_red[0];
    #pragma unroll
    for (int w = 1; w < NTHR / 32; w++) xg = fmaxf(xg, s_red[w]);

    const int ty  = threadIdx.y;
    const int tx4 = threadIdx.x * 4;
    const int co  = threadIdx.z;

    float a0 = s_b[co], a1 = a0, a2 = a0, a3 = a0;

    #pragma unroll
    for (int ci = 0; ci < 9; ci++)
        #pragma unroll
        for (int kh = 0; kh < 5; kh++) {
            const float* rowp = &s_t[ci][ty + kh][tx4];
            float4 a = *(const float4*)(rowp);
            float4 c = *(const float4*)(rowp + 4);
            float rb[8] = {a.x, a.y, a.z, a.w, c.x, c.y, c.z, c.w};
            float4 w03 = *(const float4*)&s_w4[co][ci][kh][0];
            float  w4v = s_w4[co][ci][kh][4];
            float wv[5] = {w03.x, w03.y, w03.z, w03.w, w4v};
            #pragma unroll
            for (int kw = 0; kw < 5; kw++) {
                a0 += wv[kw] * rb[kw];
                a1 += wv[kw] * rb[kw + 1];
                a2 += wv[kw] * rb[kw + 2];
                a3 += wv[kw] * rb[kw + 3];
            }
        }

    const int gy = y0 + ty, gx = x0 + tx4;
    size_t idx = (((size_t)b * CH + co) * IMGH + gy) * IMGW + gx;
    float4 xv = *(const float4*)&x[idx];
    float4 r;
    float x0v;
    x0v = fmaxf(a0, 0.f); r.x = fmaxf(xv.x * x0v + (xg - x0v), 0.f);
    x0v = fmaxf(a1, 0.f); r.y = fmaxf(xv.y * x0v + (xg - x0v), 0.f);
    x0v = fmaxf(a2, 0.f); r.z = fmaxf(xv.z * x0v + (xg - x0v), 0.f);
    x0v = fmaxf(a3, 0.f); r.w = fmaxf(xv.w * x0v + (xg - x0v), 0.f);
    *(float4*)&out[idx] = r;
}

// ---------------- launch ----------------------------------------------------
extern "C" void kernel_launch(void* const* d_in, const int* in_sizes, int n_in,
                              void* d_out, int out_size)
{
    (void)in_sizes; (void)n_in; (void)out_size;

    const float* x    = (const float*)d_in[0];
    const float* w3q  = (const float*)d_in[1];
    const float* b3q  = (const float*)d_in[2];
    const float* w3k  = (const float*)d_in[3];
    const float* w3v  = (const float*)d_in[5];
    const float* b3v  = (const float*)d_in[6];
    const float* hw3  = (const float*)d_in[7];
    const float* w6q  = (const float*)d_in[8];
    const float* b6q  = (const float*)d_in[9];
    const float* w6k  = (const float*)d_in[10];
    const float* w6v  = (const float*)d_in[12];
    const float* b6v  = (const float*)d_in[13];
    const float* hw6  = (const float*)d_in[14];
    const float* w9q  = (const float*)d_in[15];
    const float* b9q  = (const float*)d_in[16];
    const float* w9k  = (const float*)d_in[17];
    const float* w9v  = (const float*)d_in[19];
    const float* b9v  = (const float*)d_in[20];
    const float* hw9  = (const float*)d_in[21];
    const float* cw   = (const float*)d_in[22];
    const float* cb   = (const float*)d_in[23];

    float *x3, *x6, *x9;
    cudaGetSymbolAddress((void**)&x3, g_x3);
    cudaGetSymbolAddress((void**)&x6, g_x6);
    cudaGetSymbolAddress((void**)&x9, g_x9);
    float4 *G6, *gb6, *Wv6, *bv6, *G9, *gb9, *Wv9, *bv9;
    cudaGetSymbolAddress((void**)&G6,  g_G6t);
    cudaGetSymbolAddress((void**)&gb6, g_gb6);
    cudaGetSymbolAddress((void**)&Wv6, g_Wv6t);
    cudaGetSymbolAddress((void**)&bv6, g_bv6);
    cudaGetSymbolAddress((void**)&G9,  g_G9t);
    cudaGetSymbolAddress((void**)&gb9, g_gb9);
    cudaGetSymbolAddress((void**)&Wv9, g_Wv9t);
    cudaGetSymbolAddress((void**)&bv9, g_bv9);

    attn1_kernel<<<dim3(24, 24, BATCH), A1_TW * A1_TH>>>(
        x, x3, w3q, b3q, w3k, w3v, b3v, hw3,
        w6q, b6q, w6k, w6v, b6v, hw6,
        w9q, b9q, w9k, w9v, b9v, hw9);
    attn2_kernel<<<dim3(24, 24, BATCH), A2_TW * A2_TH * 4>>>(x3, x6, G6, gb6, Wv6, bv6);
    attn3_kernel<<<dim3(16, 16, BATCH), A3_TW * A3_TH * 2>>>(x6, x9, G9, gb9, Wv9, bv9);

    final_kernel<<<dim3(IMGW / FOUT_X, IMGH / FOUT_Y, BATCH), dim3(FB_X, FB_Y, 3)>>>(x, cw, cb, (float*)d_out);
}